// round 13
// baseline (speedup 1.0000x reference)
#include <cuda_runtime.h>
#include <math.h>

#define N0 4096
#define F0 512
#define H  256
#define KP1 3072
#define KP2 2304
#define KP3 1728

// ---------------- device scratch (static globals: no runtime allocation) ----------------
__device__ __align__(256) float g_feat[N0 * F0];
__device__ __align__(256) float g_A [(size_t)N0 * N0];
__device__ __align__(256) float g_A2[(size_t)N0 * N0];
__device__ __align__(256) float g_x [N0 * H];
__device__ __align__(256) float g_x2[N0 * H];
__device__ __align__(256) float g_y [N0 * H];
__device__ float g_sq[N0];
__device__ float g_dis[N0];
__device__ float g_u[N0];
__device__ float g_v[N0];
__device__ float g_score[N0];
__device__ int   g_perm[N0];
__device__ float g_vals[N0];
__device__ int   g_maxint;
__device__ float g_part[32 * 512];

// ---------------- init ----------------
__global__ void k_init(float* out) {
    int t = blockIdx.x * blockDim.x + threadIdx.x;
    if (t < 512) out[t] = 0.0f;
    if (t == 0) g_maxint = 0;
}

// ---------------- pos MLP + concat -> feat [N0, 512] ----------------
__global__ void k_posconcat(const float* __restrict__ feature,
                            const float* __restrict__ img,
                            const float* __restrict__ Wp,
                            const float* __restrict__ bp) {
    int n = blockIdx.x;
    int t = threadIdx.x;  // 128 threads
    const float* fr = feature + (size_t)n * 500;
    float* dst = g_feat + (size_t)n * F0;
    for (int i = t; i < 500; i += 128) dst[i] = fr[i];
    if (t < 12) {
        float s = bp[t];
#pragma unroll
        for (int h = 0; h < 6; h++) s += img[n * 6 + h] * Wp[h * 12 + t];
        dst[500 + t] = fmaxf(s, 0.0f);
    }
}

// ---------------- SGEMM: C[M,N] = A[M,K] @ B (BT: B is [N,K] row-major) ----------------
// EPI 0: plain store
// EPI 1: C = dis[m] * acc                         (y = dis .* (x@W))
// EPI 2: C = relu(dis[m]*(acc + ybuf[m,n]) + bias[n])   (GCN with self loop)
// LOWER: skip blocks above diagonal (Gram lower triangle only)
// TRI:   A operand strictly lower triangular -> K loop limited to m0+128
template<int EPI, bool BT, bool LOWER, bool TRI>
__global__ __launch_bounds__(256) void k_sgemm(
    const float* __restrict__ A, const float* __restrict__ B, float* __restrict__ C,
    int M, int N, int K,
    const float* __restrict__ dis, const float* __restrict__ ybuf,
    const float* __restrict__ bias)
{
    int bx = blockIdx.x, by = blockIdx.y;
    if (LOWER && bx > by) return;
    int m0 = by * 128, n0 = bx * 128;
    int Kend = TRI ? min(K, m0 + 128) : K;

    __shared__ float As[8][128];
    __shared__ float Bs[8][128];

    int tid = threadIdx.x;
    int trow = tid >> 4, tcol = tid & 15;
    float acc[8][8];
#pragma unroll
    for (int i = 0; i < 8; i++)
#pragma unroll
        for (int j = 0; j < 8; j++) acc[i][j] = 0.0f;

    int ar = tid >> 1, ac = (tid & 1) * 4;
    int brn = tid >> 5, bcn = (tid & 31) * 4;

    for (int k0 = 0; k0 < Kend; k0 += 8) {
        float4 av = *(const float4*)(A + (size_t)(m0 + ar) * K + k0 + ac);
        As[ac + 0][ar] = av.x; As[ac + 1][ar] = av.y;
        As[ac + 2][ar] = av.z; As[ac + 3][ar] = av.w;
        if (!BT) {
            float4 bv = *(const float4*)(B + (size_t)(k0 + brn) * N + n0 + bcn);
            *(float4*)&Bs[brn][bcn] = bv;
        } else {
            float4 bv = *(const float4*)(B + (size_t)(n0 + ar) * K + k0 + ac);
            Bs[ac + 0][ar] = bv.x; Bs[ac + 1][ar] = bv.y;
            Bs[ac + 2][ar] = bv.z; Bs[ac + 3][ar] = bv.w;
        }
        __syncthreads();
#pragma unroll
        for (int kk = 0; kk < 8; kk++) {
            float ra[8], rb[8];
#pragma unroll
            for (int i = 0; i < 8; i++) ra[i] = As[kk][trow * 8 + i];
#pragma unroll
            for (int j = 0; j < 8; j++) rb[j] = Bs[kk][tcol * 8 + j];
#pragma unroll
            for (int i = 0; i < 8; i++)
#pragma unroll
                for (int j = 0; j < 8; j++)
                    acc[i][j] = fmaf(ra[i], rb[j], acc[i][j]);
        }
        __syncthreads();
    }

#pragma unroll
    for (int i = 0; i < 8; i++) {
        int m = m0 + trow * 8 + i;
        float d = (EPI >= 1) ? dis[m] : 0.0f;
#pragma unroll
        for (int j = 0; j < 8; j++) {
            int n = n0 + tcol * 8 + j;
            float v = acc[i][j];
            if (EPI == 1) v = d * v;
            else if (EPI == 2) {
                v = d * (v + ybuf[(size_t)m * N + n]) + bias[n];
                v = fmaxf(v, 0.0f);
            }
            C[(size_t)m * N + n] = v;
        }
    }
}

// ---------------- diag of Gram = ||x||^2 ----------------
__global__ void k_diag() {
    int i = blockIdx.x * blockDim.x + threadIdx.x;
    if (i < N0) g_sq[i] = g_A[(size_t)i * N0 + i];
}

// ---------------- max d2 over lower triangle ----------------
__global__ void k_maxd2() {
    int j = blockIdx.x, t = threadIdx.x;
    float sj = g_sq[j];
    const float* row = g_A + (size_t)j * N0;
    float m = 0.0f;
    for (int i = t; i <= j; i += 256) {
        float d2 = sj + g_sq[i] - 2.0f * row[i];
        m = fmaxf(m, d2);
    }
    __shared__ float sm[256];
    sm[t] = m; __syncthreads();
    for (int s = 128; s > 0; s >>= 1) {
        if (t < s) sm[t] = fmaxf(sm[t], sm[t + s]);
        __syncthreads();
    }
    if (t == 0) atomicMax(&g_maxint, __float_as_int(fmaxf(sm[0], 0.0f)));
}

// ---------------- build adjacency in place + degree -> dis ----------------
__global__ void k_buildadj() {
    int j = blockIdx.x, t = threadIdx.x;
    float thr = 0.5f * __int_as_float(g_maxint);
    float sj = g_sq[j];
    float* row = g_A + (size_t)j * N0;
    float cnt = 0.0f;
    for (int i = t; i < N0; i += 256) {
        float a = 0.0f;
        if (i < j) {
            float d2 = sj + g_sq[i] - 2.0f * row[i];
            a = (d2 < thr) ? 1.0f : 0.0f;
        }
        row[i] = a;
        cnt += a;
    }
    __shared__ float sm[256];
    sm[t] = cnt; __syncthreads();
    for (int s = 128; s > 0; s >>= 1) {
        if (t < s) sm[t] += sm[t + s];
        __syncthreads();
    }
    if (t == 0) g_dis[j] = rsqrtf(1.0f + sm[0]);
}

// ---------------- scorer matvecs: u = x@Wn, v = x@Wr ----------------
__global__ void k_scorevec(const float* __restrict__ x,
                           const float* __restrict__ Wn,
                           const float* __restrict__ Wr) {
    int j = blockIdx.x, t = threadIdx.x;  // 256 threads
    float p = x[(size_t)j * H + t];
    float uu = p * Wn[t], vv = p * Wr[t];
    __shared__ float su[256], sv[256];
    su[t] = uu; sv[t] = vv; __syncthreads();
    for (int s = 128; s > 0; s >>= 1) {
        if (t < s) { su[t] += su[t + s]; sv[t] += sv[t + s]; }
        __syncthreads();
    }
    if (t == 0) { g_u[j] = su[0]; g_v[j] = sv[0]; }
}

// ---------------- w = A@u (A strictly lower), score = tanh(w + bs + v) ----------------
__global__ void k_auscore(const float* __restrict__ Aadj,
                          const float* __restrict__ bsp, int Nl) {
    int j = blockIdx.x, t = threadIdx.x;
    const float* row = Aadj + (size_t)j * Nl;
    float s = 0.0f;
    for (int i = t; i < j; i += 256) s += row[i] * g_u[i];
    __shared__ float sm[256];
    sm[t] = s; __syncthreads();
    for (int st = 128; st > 0; st >>= 1) {
        if (t < st) sm[t] += sm[t + st];
        __syncthreads();
    }
    if (t == 0) g_score[j] = tanhf(sm[0] + bsp[0] + g_v[j]);
}

// ---------------- top-k via bitonic sort (1 block, 1024 threads, P=4096) ----------------
__device__ void bitonic4096(float* ss, int* si, bool byScore) {
    int t = threadIdx.x;
    for (int size = 2; size <= 4096; size <<= 1) {
        for (int stride = size >> 1; stride > 0; stride >>= 1) {
            __syncthreads();
            for (int p = t; p < 2048; p += 1024) {
                int i = ((p / stride) * (stride << 1)) + (p % stride);
                int j = i + stride;
                bool dirUp = ((i & size) == 0);
                float sa = ss[i], sb = ss[j];
                int ia = si[i], ib = si[j];
                // b true if j-element precedes i-element in target order
                bool b = byScore ? ((sb > sa) || (sb == sa && ib < ia)) : (ib < ia);
                if (b == dirUp) {
                    ss[i] = sb; ss[j] = sa;
                    si[i] = ib; si[j] = ia;
                }
            }
        }
    }
    __syncthreads();
}

__global__ __launch_bounds__(1024) void k_topk(int Nl, int k) {
    __shared__ float ss[4096];
    __shared__ int   si[4096];
    int t = threadIdx.x;
    for (int i = t; i < 4096; i += 1024) {
        if (i < Nl) { ss[i] = g_score[i]; si[i] = i; }
        else        { ss[i] = __int_as_float(0xff800000); si[i] = 0x7FFFFFFF; }
    }
    __syncthreads();
    // phase 1: descending by score (tie -> smaller index), matches lax.top_k set
    bitonic4096(ss, si, true);
    // phase 2: keep first k, re-sort selected by index ascending (keeps A triangular)
    for (int i = t; i < 4096; i += 1024)
        if (i >= k) si[i] = 0x7FFFFFFF;
    __syncthreads();
    bitonic4096(ss, si, false);
    for (int r = t; r < k; r += 1024) { g_perm[r] = si[r]; g_vals[r] = ss[r]; }
}

// ---------------- gather x: xp[r] = x[perm[r]] * vals[r] ----------------
__global__ void k_gatherx(const float* __restrict__ xin, float* __restrict__ xout, int k) {
    int r = blockIdx.x, t = threadIdx.x;
    int pr = g_perm[r];
    float v = g_vals[r];
    xout[(size_t)r * H + t] = xin[(size_t)pr * H + t] * v;
}

// ---------------- gather A (stays strictly lower) + new degrees ----------------
__global__ void k_gatherA(const float* __restrict__ Ain, float* __restrict__ Aout,
                          int Nin, int k) {
    int r = blockIdx.x, t = threadIdx.x;
    int pr = g_perm[r];
    const float* rin = Ain + (size_t)pr * Nin;
    float* rout = Aout + (size_t)r * k;
    float cnt = 0.0f;
    for (int c = t; c < k; c += 256) {
        float a = (c < r) ? rin[g_perm[c]] : 0.0f;
        rout[c] = a;
        cnt += a;
    }
    __shared__ float sm[256];
    sm[t] = cnt; __syncthreads();
    for (int s = 128; s > 0; s >>= 1) {
        if (t < s) sm[t] += sm[t + s];
        __syncthreads();
    }
    if (t == 0) g_dis[r] = rsqrtf(1.0f + sm[0]);
}

// ---------------- readout: column max + sum -> accumulate into out ----------------
__global__ void k_readout_part(const float* __restrict__ x, int k) {
    int b = blockIdx.x, t = threadIdx.x;  // grid 32, 256 threads
    float mx = __int_as_float(0xff800000), sm = 0.0f;
    for (int r = b; r < k; r += 32) {
        float v = x[(size_t)r * H + t];
        mx = fmaxf(mx, v);
        sm += v;
    }
    g_part[b * 512 + t] = mx;
    g_part[b * 512 + 256 + t] = sm;
}

__global__ void k_readout_final(float* out, float invk) {
    int t = threadIdx.x;  // 256
    float mx = __int_as_float(0xff800000), sm = 0.0f;
    for (int b = 0; b < 32; b++) {
        mx = fmaxf(mx, g_part[b * 512 + t]);
        sm += g_part[b * 512 + 256 + t];
    }
    out[t] += mx;
    out[256 + t] += sm * invk;
}

// ---------------- one GCN + SAGPool + readout layer ----------------
static void run_layer(const float* xin, int Kin, const float* Ain, int Nl,
                      const float* W, const float* bvec,
                      const float* Wr, const float* Wn, const float* bs,
                      int k, float* xnew, float* xpool, float* Apool,
                      float* ybuf, const float* pdis, float* d_out)
{
    // y = dis .* (x @ W)
    {
        dim3 g(H / 128, Nl / 128);
        k_sgemm<1, false, false, false><<<g, 256>>>(xin, W, ybuf, Nl, H, Kin,
                                                    pdis, nullptr, nullptr);
    }
    // xnew = relu(dis .* (A@y + y) + b)   [A strictly lower -> TRI K-limit]
    {
        dim3 g(H / 128, Nl / 128);
        k_sgemm<2, false, false, true><<<g, 256>>>(Ain, ybuf, xnew, Nl, H, Nl,
                                                   pdis, ybuf, bvec);
    }
    k_scorevec<<<Nl, 256>>>(xnew, Wn, Wr);
    k_auscore<<<Nl, 256>>>(Ain, bs, Nl);
    k_topk<<<1, 1024>>>(Nl, k);
    k_gatherx<<<k, 256>>>(xnew, xpool, k);
    k_gatherA<<<k, 256>>>(Ain, Apool, Nl, k);
    k_readout_part<<<32, 256>>>(xpool, k);
    k_readout_final<<<1, 256>>>(d_out, 1.0f / (float)k);
}

extern "C" void kernel_launch(void* const* d_in, const int* in_sizes, int n_in,
                              void* d_out, int out_size) {
    const float* feature = (const float*)d_in[0];
    const float* img     = (const float*)d_in[1];
    const float* W_pos   = (const float*)d_in[2];
    const float* b_pos   = (const float*)d_in[3];
    const float* W1 = (const float*)d_in[4];  const float* b1 = (const float*)d_in[5];
    const float* W2 = (const float*)d_in[6];  const float* b2 = (const float*)d_in[7];
    const float* W3 = (const float*)d_in[8];  const float* b3 = (const float*)d_in[9];
    const float* Wr1 = (const float*)d_in[10]; const float* Wn1 = (const float*)d_in[11];
    const float* bs1 = (const float*)d_in[12];
    const float* Wr2 = (const float*)d_in[13]; const float* Wn2 = (const float*)d_in[14];
    const float* bs2 = (const float*)d_in[15];
    const float* Wr3 = (const float*)d_in[16]; const float* Wn3 = (const float*)d_in[17];
    const float* bs3 = (const float*)d_in[18];
    float* out = (float*)d_out;

    float *pfeat, *pA, *pA2, *px, *px2, *py, *pdis;
    cudaGetSymbolAddress((void**)&pfeat, g_feat);
    cudaGetSymbolAddress((void**)&pA,   g_A);
    cudaGetSymbolAddress((void**)&pA2,  g_A2);
    cudaGetSymbolAddress((void**)&px,   g_x);
    cudaGetSymbolAddress((void**)&px2,  g_x2);
    cudaGetSymbolAddress((void**)&py,   g_y);
    cudaGetSymbolAddress((void**)&pdis, g_dis);   // FIX: device address, not host shadow

    k_init<<<2, 256>>>(out);
    k_posconcat<<<N0, 128>>>(feature, img, W_pos, b_pos);

    // Gram (lower triangle + diagonal only): G = feat @ feat^T into g_A
    {
        dim3 g(N0 / 128, N0 / 128);
        k_sgemm<0, true, true, false><<<g, 256>>>(pfeat, pfeat, pA, N0, N0, F0,
                                                  nullptr, nullptr, nullptr);
    }
    k_diag<<<N0 / 256, 256>>>();
    k_maxd2<<<N0, 256>>>();
    k_buildadj<<<N0, 256>>>();

    // layer 1: A in g_A (4096), pool -> x2 (3072), A -> g_A2
    run_layer(pfeat, F0, pA, N0, W1, b1, Wr1, Wn1, bs1, KP1, px, px2, pA2, py, pdis, out);
    // layer 2: A in g_A2 (3072), pool -> x2 (2304), A -> g_A
    run_layer(px2, H, pA2, KP1, W2, b2, Wr2, Wn2, bs2, KP2, px, px2, pA, py, pdis, out);
    // layer 3: A in g_A (2304), pool -> x2 (1728), A -> g_A2
    run_layer(px2, H, pA, KP2, W3, b3, Wr3, Wn3, bs3, KP3, px, px2, pA2, py, pdis, out);
}

// round 14
// speedup vs baseline: 2.7246x; 2.7246x over previous
#include <cuda_runtime.h>
#include <math.h>

#define N0 4096
#define F0 512
#define H  256
#define KP1 3072
#define KP2 2304
#define KP3 1728
#define MAXE (N0*(N0-1)/2)   // 8,386,560 max strictly-lower edges

// ---------------- device scratch (static globals: no runtime allocation) ----------------
__device__ __align__(256) float g_feat[N0 * F0];
__device__ __align__(256) float g_A [(size_t)N0 * N0];   // Gram matrix (lower tri valid)
__device__ __align__(256) float g_x [N0 * H];
__device__ __align__(256) float g_x2[N0 * H];
__device__ __align__(256) float g_y [N0 * H];
__device__ float g_sq[N0];
__device__ float g_dis[N0];
__device__ float g_u[N0];
__device__ float g_v[N0];
__device__ float g_score[N0];
__device__ int   g_perm[N0];
__device__ float g_vals[N0];
__device__ int   g_maxint;
__device__ float g_part[32 * 512];
// CSR adjacency (double-buffered across layers)
__device__ int g_colA[MAXE];
__device__ int g_colB[MAXE];
__device__ int g_rpA[N0 + 1];
__device__ int g_rpB[N0 + 1];
__device__ int g_deg[N0];
__device__ int g_inv[N0];

// ---------------- init ----------------
__global__ void k_init(float* out) {
    int t = blockIdx.x * blockDim.x + threadIdx.x;
    if (t < 512) out[t] = 0.0f;
    if (t == 0) g_maxint = 0;
}

// ---------------- pos MLP + concat -> feat [N0, 512] ----------------
__global__ void k_posconcat(const float* __restrict__ feature,
                            const float* __restrict__ img,
                            const float* __restrict__ Wp,
                            const float* __restrict__ bp) {
    int n = blockIdx.x;
    int t = threadIdx.x;  // 128 threads
    const float* fr = feature + (size_t)n * 500;
    float* dst = g_feat + (size_t)n * F0;
    for (int i = t; i < 500; i += 128) dst[i] = fr[i];
    if (t < 12) {
        float s = bp[t];
#pragma unroll
        for (int h = 0; h < 6; h++) s += img[n * 6 + h] * Wp[h * 12 + t];
        dst[500 + t] = fmaxf(s, 0.0f);
    }
}

// ---------------- SGEMM: C[M,N] = A[M,K] @ B (BT: B is [N,K] row-major) ----------------
// EPI 0: plain store
// EPI 1: C = dis[m] * acc        (y = dis .* (x@W))
// LOWER: skip blocks above diagonal (Gram lower triangle only)
template<int EPI, bool BT, bool LOWER>
__global__ __launch_bounds__(256) void k_sgemm(
    const float* __restrict__ A, const float* __restrict__ B, float* __restrict__ C,
    int M, int N, int K, const float* __restrict__ dis)
{
    int bx = blockIdx.x, by = blockIdx.y;
    if (LOWER && bx > by) return;
    int m0 = by * 128, n0 = bx * 128;

    __shared__ float As[8][128];
    __shared__ float Bs[8][128];

    int tid = threadIdx.x;
    int trow = tid >> 4, tcol = tid & 15;
    float acc[8][8];
#pragma unroll
    for (int i = 0; i < 8; i++)
#pragma unroll
        for (int j = 0; j < 8; j++) acc[i][j] = 0.0f;

    int ar = tid >> 1, ac = (tid & 1) * 4;
    int brn = tid >> 5, bcn = (tid & 31) * 4;

    for (int k0 = 0; k0 < K; k0 += 8) {
        float4 av = *(const float4*)(A + (size_t)(m0 + ar) * K + k0 + ac);
        As[ac + 0][ar] = av.x; As[ac + 1][ar] = av.y;
        As[ac + 2][ar] = av.z; As[ac + 3][ar] = av.w;
        if (!BT) {
            float4 bv = *(const float4*)(B + (size_t)(k0 + brn) * N + n0 + bcn);
            *(float4*)&Bs[brn][bcn] = bv;
        } else {
            float4 bv = *(const float4*)(B + (size_t)(n0 + ar) * K + k0 + ac);
            Bs[ac + 0][ar] = bv.x; Bs[ac + 1][ar] = bv.y;
            Bs[ac + 2][ar] = bv.z; Bs[ac + 3][ar] = bv.w;
        }
        __syncthreads();
#pragma unroll
        for (int kk = 0; kk < 8; kk++) {
            float ra[8], rb[8];
#pragma unroll
            for (int i = 0; i < 8; i++) ra[i] = As[kk][trow * 8 + i];
#pragma unroll
            for (int j = 0; j < 8; j++) rb[j] = Bs[kk][tcol * 8 + j];
#pragma unroll
            for (int i = 0; i < 8; i++)
#pragma unroll
                for (int j = 0; j < 8; j++)
                    acc[i][j] = fmaf(ra[i], rb[j], acc[i][j]);
        }
        __syncthreads();
    }

#pragma unroll
    for (int i = 0; i < 8; i++) {
        int m = m0 + trow * 8 + i;
        float d = (EPI == 1) ? dis[m] : 0.0f;
#pragma unroll
        for (int j = 0; j < 8; j++) {
            int n = n0 + tcol * 8 + j;
            float v = acc[i][j];
            if (EPI == 1) v = d * v;
            C[(size_t)m * N + n] = v;
        }
    }
}

// ---------------- diag of Gram = ||x||^2 ----------------
__global__ void k_diag() {
    int i = blockIdx.x * blockDim.x + threadIdx.x;
    if (i < N0) g_sq[i] = g_A[(size_t)i * N0 + i];
}

// ---------------- max d2 over lower triangle ----------------
__global__ void k_maxd2() {
    int j = blockIdx.x, t = threadIdx.x;
    float sj = g_sq[j];
    const float* row = g_A + (size_t)j * N0;
    float m = 0.0f;
    for (int i = t; i <= j; i += 256) {
        float d2 = sj + g_sq[i] - 2.0f * row[i];
        m = fmaxf(m, d2);
    }
    __shared__ float sm[256];
    sm[t] = m; __syncthreads();
    for (int s = 128; s > 0; s >>= 1) {
        if (t < s) sm[t] = fmaxf(sm[t], sm[t + s]);
        __syncthreads();
    }
    if (t == 0) atomicMax(&g_maxint, __float_as_int(fmaxf(sm[0], 0.0f)));
}

// ---------------- degree count per row (predicate on Gram, no dense A store) ----------------
__global__ void k_degree() {
    int j = blockIdx.x, t = threadIdx.x;
    float thr = 0.5f * __int_as_float(g_maxint);
    float sj = g_sq[j];
    const float* row = g_A + (size_t)j * N0;
    int cnt = 0;
    for (int i = t; i < j; i += 256)
        cnt += (sj + g_sq[i] - 2.0f * row[i] < thr) ? 1 : 0;
    __shared__ int sm[256];
    sm[t] = cnt; __syncthreads();
    for (int s = 128; s > 0; s >>= 1) {
        if (t < s) sm[t] += sm[t + s];
        __syncthreads();
    }
    if (t == 0) { g_deg[j] = sm[0]; g_dis[j] = rsqrtf(1.0f + (float)sm[0]); }
}

// ---------------- exclusive scan of degrees -> row pointers (single block) ----------------
__global__ __launch_bounds__(1024) void k_scan(const int* __restrict__ deg,
                                               int* __restrict__ rp, int n) {
    __shared__ int s[1024];
    int t = threadIdx.x;
    int base = t * 4;
    int v[4]; int local = 0;
#pragma unroll
    for (int q = 0; q < 4; q++) {
        int idx = base + q;
        v[q] = (idx < n) ? deg[idx] : 0;
        local += v[q];
    }
    s[t] = local; __syncthreads();
    for (int off = 1; off < 1024; off <<= 1) {
        int val = (t >= off) ? s[t - off] : 0;
        __syncthreads();
        s[t] += val;
        __syncthreads();
    }
    int run = (t == 0) ? 0 : s[t - 1];
#pragma unroll
    for (int q = 0; q < 4; q++) {
        int idx = base + q;
        if (idx < n) rp[idx] = run;
        run += v[q];
    }
    if (t == 1023) rp[n] = s[1023];
}

// ---------------- fill initial CSR: warp per row, ordered ballot compaction ----------------
__global__ void k_fillcsr(const int* __restrict__ rp, int* __restrict__ col, int Nl) {
    int w = (blockIdx.x * blockDim.x + threadIdx.x) >> 5;
    int lane = threadIdx.x & 31;
    if (w >= Nl) return;
    float thr = 0.5f * __int_as_float(g_maxint);
    float sj = g_sq[w];
    const float* row = g_A + (size_t)w * N0;
    int base = rp[w];
    for (int i0 = 0; i0 < w; i0 += 32) {
        int i = i0 + lane;
        bool pred = (i < w) && (sj + g_sq[i] - 2.0f * row[i] < thr);
        unsigned mask = __ballot_sync(0xFFFFFFFFu, pred);
        if (pred) col[base + __popc(mask & ((1u << lane) - 1u))] = i;
        base += __popc(mask);
    }
}

// ---------------- SpMM + GCN epilogue: xnew = relu(dis*(sum_nbr y + y) + b) ----------------
__global__ void k_spmm(const int* __restrict__ rp, const int* __restrict__ col,
                       const float* __restrict__ y, float* __restrict__ xnew,
                       const float* __restrict__ bias) {
    int j = blockIdx.x, t = threadIdx.x;  // 256 threads = H
    int p = rp[j], e = rp[j + 1];
    float acc = y[(size_t)j * H + t];     // self loop
    for (; p + 4 <= e; p += 4) {
        int c0 = col[p], c1 = col[p + 1], c2 = col[p + 2], c3 = col[p + 3];
        acc += y[(size_t)c0 * H + t] + y[(size_t)c1 * H + t]
             + y[(size_t)c2 * H + t] + y[(size_t)c3 * H + t];
    }
    for (; p < e; ++p) acc += y[(size_t)col[p] * H + t];
    xnew[(size_t)j * H + t] = fmaxf(g_dis[j] * acc + bias[t], 0.0f);
}

// ---------------- scorer matvecs: u = x@Wn, v = x@Wr ----------------
__global__ void k_scorevec(const float* __restrict__ x,
                           const float* __restrict__ Wn,
                           const float* __restrict__ Wr) {
    int j = blockIdx.x, t = threadIdx.x;  // 256 threads
    float p = x[(size_t)j * H + t];
    float uu = p * Wn[t], vv = p * Wr[t];
    __shared__ float su[256], sv[256];
    su[t] = uu; sv[t] = vv; __syncthreads();
    for (int s = 128; s > 0; s >>= 1) {
        if (t < s) { su[t] += su[t + s]; sv[t] += sv[t + s]; }
        __syncthreads();
    }
    if (t == 0) { g_u[j] = su[0]; g_v[j] = sv[0]; }
}

// ---------------- score = tanh(A@u + bs + v): warp per row over CSR ----------------
__global__ void k_auscore(const int* __restrict__ rp, const int* __restrict__ col,
                          const float* __restrict__ bsp, int Nl) {
    int w = (blockIdx.x * blockDim.x + threadIdx.x) >> 5;
    int lane = threadIdx.x & 31;
    if (w >= Nl) return;
    int s = rp[w], e = rp[w + 1];
    float acc = 0.0f;
    for (int p = s + lane; p < e; p += 32) acc += g_u[col[p]];
    for (int off = 16; off; off >>= 1) acc += __shfl_down_sync(0xFFFFFFFFu, acc, off);
    if (lane == 0) g_score[w] = tanhf(acc + bsp[0] + g_v[w]);
}

// ---------------- top-k via bitonic sort (1 block, 1024 threads, P=4096) ----------------
__device__ void bitonic4096(float* ss, int* si, bool byScore) {
    int t = threadIdx.x;
    for (int size = 2; size <= 4096; size <<= 1) {
        for (int stride = size >> 1; stride > 0; stride >>= 1) {
            __syncthreads();
            for (int p = t; p < 2048; p += 1024) {
                int i = ((p / stride) * (stride << 1)) + (p % stride);
                int j = i + stride;
                bool dirUp = ((i & size) == 0);
                float sa = ss[i], sb = ss[j];
                int ia = si[i], ib = si[j];
                bool b = byScore ? ((sb > sa) || (sb == sa && ib < ia)) : (ib < ia);
                if (b == dirUp) {
                    ss[i] = sb; ss[j] = sa;
                    si[i] = ib; si[j] = ia;
                }
            }
        }
    }
    __syncthreads();
}

__global__ __launch_bounds__(1024) void k_topk(int Nl, int k) {
    __shared__ float ss[4096];
    __shared__ int   si[4096];
    int t = threadIdx.x;
    for (int i = t; i < 4096; i += 1024) {
        if (i < Nl) { ss[i] = g_score[i]; si[i] = i; }
        else        { ss[i] = __int_as_float(0xff800000); si[i] = 0x7FFFFFFF; }
    }
    __syncthreads();
    bitonic4096(ss, si, true);   // descending by score (tie -> smaller index)
    for (int i = t; i < 4096; i += 1024)
        if (i >= k) si[i] = 0x7FFFFFFF;
    __syncthreads();
    bitonic4096(ss, si, false);  // selected k re-sorted ascending by index
    for (int r = t; r < k; r += 1024) { g_perm[r] = si[r]; g_vals[r] = ss[r]; }
}

// ---------------- gather x: xp[r] = x[perm[r]] * vals[r] ----------------
__global__ void k_gatherx(const float* __restrict__ xin, float* __restrict__ xout, int k) {
    int r = blockIdx.x, t = threadIdx.x;
    int pr = g_perm[r];
    float v = g_vals[r];
    xout[(size_t)r * H + t] = xin[(size_t)pr * H + t] * v;
}

// ---------------- inverse permutation ----------------
__global__ void k_invreset(int Nl) {
    int i = blockIdx.x * blockDim.x + threadIdx.x;
    if (i < Nl) g_inv[i] = -1;
}
__global__ void k_invset(int k) {
    int r = blockIdx.x * blockDim.x + threadIdx.x;
    if (r < k) g_inv[g_perm[r]] = r;
}

// ---------------- pooled CSR: count surviving neighbors per pooled row ----------------
__global__ void k_deg2(const int* __restrict__ rpIn, const int* __restrict__ colIn, int k) {
    int w = (blockIdx.x * blockDim.x + threadIdx.x) >> 5;
    int lane = threadIdx.x & 31;
    if (w >= k) return;
    int pr = g_perm[w];
    int s = rpIn[pr], e = rpIn[pr + 1];
    int cnt = 0;
    for (int p = s + lane; p < e; p += 32) cnt += (g_inv[colIn[p]] >= 0) ? 1 : 0;
    for (int off = 16; off; off >>= 1) cnt += __shfl_down_sync(0xFFFFFFFFu, cnt, off);
    if (lane == 0) { g_deg[w] = cnt; g_dis[w] = rsqrtf(1.0f + (float)cnt); }
}

// ---------------- pooled CSR: fill (ordered; ascending old -> ascending new) ----------------
__global__ void k_fill2(const int* __restrict__ rpIn, const int* __restrict__ colIn,
                        const int* __restrict__ rpOut, int* __restrict__ colOut, int k) {
    int w = (blockIdx.x * blockDim.x + threadIdx.x) >> 5;
    int lane = threadIdx.x & 31;
    if (w >= k) return;
    int pr = g_perm[w];
    int s = rpIn[pr], e = rpIn[pr + 1];
    int base = rpOut[w];
    for (int p0 = s; p0 < e; p0 += 32) {
        int p = p0 + lane;
        int m = -1;
        bool pred = false;
        if (p < e) { m = g_inv[colIn[p]]; pred = (m >= 0); }
        unsigned mask = __ballot_sync(0xFFFFFFFFu, pred);
        if (pred) colOut[base + __popc(mask & ((1u << lane) - 1u))] = m;
        base += __popc(mask);
    }
}

// ---------------- readout: column max + sum -> accumulate into out ----------------
__global__ void k_readout_part(const float* __restrict__ x, int k) {
    int b = blockIdx.x, t = threadIdx.x;  // grid 32, 256 threads
    float mx = __int_as_float(0xff800000), sm = 0.0f;
    for (int r = b; r < k; r += 32) {
        float v = x[(size_t)r * H + t];
        mx = fmaxf(mx, v);
        sm += v;
    }
    g_part[b * 512 + t] = mx;
    g_part[b * 512 + 256 + t] = sm;
}

__global__ void k_readout_final(float* out, float invk) {
    int t = threadIdx.x;  // 256
    float mx = __int_as_float(0xff800000), sm = 0.0f;
    for (int b = 0; b < 32; b++) {
        mx = fmaxf(mx, g_part[b * 512 + t]);
        sm += g_part[b * 512 + 256 + t];
    }
    out[t] += mx;
    out[256 + t] += sm * invk;
}

// ---------------- one GCN + SAGPool + readout layer (CSR adjacency) ----------------
static void run_layer(const float* xin, int Kin, const int* rpIn, const int* colIn, int Nl,
                      const float* W, const float* bvec,
                      const float* Wr, const float* Wn, const float* bs,
                      int k, float* xnew, float* xpool,
                      int* rpOut, int* colOut, int* pdeg,
                      float* ybuf, const float* pdis, float* d_out)
{
    // y = dis .* (x @ W)
    {
        dim3 g(H / 128, Nl / 128);
        k_sgemm<1, false, false><<<g, 256>>>(xin, W, ybuf, Nl, H, Kin, pdis);
    }
    // xnew = relu(dis .* (A@y + y) + b)  via CSR SpMM
    k_spmm<<<Nl, 256>>>(rpIn, colIn, ybuf, xnew, bvec);
    k_scorevec<<<Nl, 256>>>(xnew, Wn, Wr);
    k_auscore<<<(Nl + 7) / 8, 256>>>(rpIn, colIn, bs, Nl);
    k_topk<<<1, 1024>>>(Nl, k);
    k_gatherx<<<k, 256>>>(xnew, xpool, k);
    // pooled CSR
    k_invreset<<<(Nl + 255) / 256, 256>>>(Nl);
    k_invset<<<(k + 255) / 256, 256>>>(k);
    k_deg2<<<(k + 7) / 8, 256>>>(rpIn, colIn, k);
    k_scan<<<1, 1024>>>(pdeg, rpOut, k);
    k_fill2<<<(k + 7) / 8, 256>>>(rpIn, colIn, rpOut, colOut, k);
    // readout accumulate
    k_readout_part<<<32, 256>>>(xpool, k);
    k_readout_final<<<1, 256>>>(d_out, 1.0f / (float)k);
}

extern "C" void kernel_launch(void* const* d_in, const int* in_sizes, int n_in,
                              void* d_out, int out_size) {
    const float* feature = (const float*)d_in[0];
    const float* img     = (const float*)d_in[1];
    const float* W_pos   = (const float*)d_in[2];
    const float* b_pos   = (const float*)d_in[3];
    const float* W1 = (const float*)d_in[4];  const float* b1 = (const float*)d_in[5];
    const float* W2 = (const float*)d_in[6];  const float* b2 = (const float*)d_in[7];
    const float* W3 = (const float*)d_in[8];  const float* b3 = (const float*)d_in[9];
    const float* Wr1 = (const float*)d_in[10]; const float* Wn1 = (const float*)d_in[11];
    const float* bs1 = (const float*)d_in[12];
    const float* Wr2 = (const float*)d_in[13]; const float* Wn2 = (const float*)d_in[14];
    const float* bs2 = (const float*)d_in[15];
    const float* Wr3 = (const float*)d_in[16]; const float* Wn3 = (const float*)d_in[17];
    const float* bs3 = (const float*)d_in[18];
    float* out = (float*)d_out;

    float *pfeat, *pA, *px, *px2, *py, *pdis;
    int *pcolA, *pcolB, *prpA, *prpB, *pdeg;
    cudaGetSymbolAddress((void**)&pfeat, g_feat);
    cudaGetSymbolAddress((void**)&pA,    g_A);
    cudaGetSymbolAddress((void**)&px,    g_x);
    cudaGetSymbolAddress((void**)&px2,   g_x2);
    cudaGetSymbolAddress((void**)&py,    g_y);
    cudaGetSymbolAddress((void**)&pdis,  g_dis);
    cudaGetSymbolAddress((void**)&pcolA, g_colA);
    cudaGetSymbolAddress((void**)&pcolB, g_colB);
    cudaGetSymbolAddress((void**)&prpA,  g_rpA);
    cudaGetSymbolAddress((void**)&prpB,  g_rpB);
    cudaGetSymbolAddress((void**)&pdeg,  g_deg);

    k_init<<<2, 256>>>(out);
    k_posconcat<<<N0, 128>>>(feature, img, W_pos, b_pos);

    // Gram (lower triangle + diagonal blocks): G = feat @ feat^T into g_A
    {
        dim3 g(N0 / 128, N0 / 128);
        k_sgemm<0, true, true><<<g, 256>>>(pfeat, pfeat, pA, N0, N0, F0, nullptr);
    }
    k_diag<<<N0 / 256, 256>>>();
    k_maxd2<<<N0, 256>>>();
    // adjacency directly to CSR (Gram read twice, never overwritten)
    k_degree<<<N0, 256>>>();
    k_scan<<<1, 1024>>>(pdeg, prpA, N0);
    k_fillcsr<<<N0 / 8, 256>>>(prpA, pcolA, N0);

    // layer 1: CSR A (4096) -> pooled CSR B (3072)
    run_layer(pfeat, F0, prpA, pcolA, N0,  W1, b1, Wr1, Wn1, bs1, KP1,
              px, px2, prpB, pcolB, pdeg, py, pdis, out);
    // layer 2: CSR B (3072) -> pooled CSR A (2304)
    run_layer(px2, H, prpB, pcolB, KP1, W2, b2, Wr2, Wn2, bs2, KP2,
              px, px2, prpA, pcolA, pdeg, py, pdis, out);
    // layer 3: CSR A (2304) -> pooled CSR B (1728)
    run_layer(px2, H, prpA, pcolA, KP2, W3, b3, Wr3, Wn3, bs3, KP3,
              px, px2, prpB, pcolB, pdeg, py, pdis, out);
}

// round 15
// speedup vs baseline: 2.7252x; 1.0002x over previous
#include <cuda_runtime.h>
#include <math.h>

#define N0 4096
#define F0 512
#define H  256
#define KP1 3072
#define KP2 2304
#define KP3 1728
#define MAXE (N0*(N0-1)/2)   // 8,386,560 max strictly-lower edges

// ---------------- device scratch (static globals: no runtime allocation) ----------------
__device__ __align__(256) float g_feat[N0 * F0];
__device__ __align__(256) float g_A [(size_t)N0 * N0];   // Gram matrix (lower tri valid)
__device__ __align__(256) float g_x [N0 * H];
__device__ __align__(256) float g_x2[N0 * H];
__device__ __align__(256) float g_y [N0 * H];
__device__ float g_sq[N0];
__device__ float g_dis[N0];
__device__ float g_u[N0];
__device__ float g_v[N0];
__device__ float g_score[N0];
__device__ int   g_perm[N0];
__device__ float g_vals[N0];
__device__ int   g_maxint;
__device__ float g_part[32 * 512];
// CSR adjacency (double-buffered across layers)
__device__ int g_colA[MAXE];
__device__ int g_colB[MAXE];
__device__ int g_rpA[N0 + 1];
__device__ int g_rpB[N0 + 1];
__device__ int g_deg[N0];
__device__ int g_inv[N0];

// ---------------- init ----------------
__global__ void k_init(float* out) {
    int t = blockIdx.x * blockDim.x + threadIdx.x;
    if (t < 512) out[t] = 0.0f;
    if (t == 0) g_maxint = 0;
}

// ---------------- pos MLP + concat -> feat [N0, 512] ----------------
__global__ void k_posconcat(const float* __restrict__ feature,
                            const float* __restrict__ img,
                            const float* __restrict__ Wp,
                            const float* __restrict__ bp) {
    int n = blockIdx.x;
    int t = threadIdx.x;  // 128 threads
    const float* fr = feature + (size_t)n * 500;
    float* dst = g_feat + (size_t)n * F0;
    for (int i = t; i < 500; i += 128) dst[i] = fr[i];
    if (t < 12) {
        float s = bp[t];
#pragma unroll
        for (int h = 0; h < 6; h++) s += img[n * 6 + h] * Wp[h * 12 + t];
        dst[500 + t] = fmaxf(s, 0.0f);
    }
}

// ---------------- SGEMM: C[M,N] = A[M,K] @ B (BT: B is [N,K] row-major) ----------------
// EPI 0: plain store
// EPI 1: C = dis[m] * acc        (y = dis .* (x@W))
// LOWER: skip blocks above diagonal (Gram lower triangle only)
template<int EPI, bool BT, bool LOWER>
__global__ __launch_bounds__(256) void k_sgemm(
    const float* __restrict__ A, const float* __restrict__ B, float* __restrict__ C,
    int M, int N, int K, const float* __restrict__ dis)
{
    int bx = blockIdx.x, by = blockIdx.y;
    if (LOWER && bx > by) return;
    int m0 = by * 128, n0 = bx * 128;

    __shared__ float As[8][128];
    __shared__ float Bs[8][128];

    int tid = threadIdx.x;
    int trow = tid >> 4, tcol = tid & 15;
    float acc[8][8];
#pragma unroll
    for (int i = 0; i < 8; i++)
#pragma unroll
        for (int j = 0; j < 8; j++) acc[i][j] = 0.0f;

    int ar = tid >> 1, ac = (tid & 1) * 4;
    int brn = tid >> 5, bcn = (tid & 31) * 4;

    for (int k0 = 0; k0 < K; k0 += 8) {
        float4 av = *(const float4*)(A + (size_t)(m0 + ar) * K + k0 + ac);
        As[ac + 0][ar] = av.x; As[ac + 1][ar] = av.y;
        As[ac + 2][ar] = av.z; As[ac + 3][ar] = av.w;
        if (!BT) {
            float4 bv = *(const float4*)(B + (size_t)(k0 + brn) * N + n0 + bcn);
            *(float4*)&Bs[brn][bcn] = bv;
        } else {
            float4 bv = *(const float4*)(B + (size_t)(n0 + ar) * K + k0 + ac);
            Bs[ac + 0][ar] = bv.x; Bs[ac + 1][ar] = bv.y;
            Bs[ac + 2][ar] = bv.z; Bs[ac + 3][ar] = bv.w;
        }
        __syncthreads();
#pragma unroll
        for (int kk = 0; kk < 8; kk++) {
            float ra[8], rb[8];
#pragma unroll
            for (int i = 0; i < 8; i++) ra[i] = As[kk][trow * 8 + i];
#pragma unroll
            for (int j = 0; j < 8; j++) rb[j] = Bs[kk][tcol * 8 + j];
#pragma unroll
            for (int i = 0; i < 8; i++)
#pragma unroll
                for (int j = 0; j < 8; j++)
                    acc[i][j] = fmaf(ra[i], rb[j], acc[i][j]);
        }
        __syncthreads();
    }

#pragma unroll
    for (int i = 0; i < 8; i++) {
        int m = m0 + trow * 8 + i;
        float d = (EPI == 1) ? dis[m] : 0.0f;
#pragma unroll
        for (int j = 0; j < 8; j++) {
            int n = n0 + tcol * 8 + j;
            float v = acc[i][j];
            if (EPI == 1) v = d * v;
            C[(size_t)m * N + n] = v;
        }
    }
}

// ---------------- diag of Gram = ||x||^2 ----------------
__global__ void k_diag() {
    int i = blockIdx.x * blockDim.x + threadIdx.x;
    if (i < N0) g_sq[i] = g_A[(size_t)i * N0 + i];
}

// ---------------- max d2 over lower triangle ----------------
__global__ void k_maxd2() {
    int j = blockIdx.x, t = threadIdx.x;
    float sj = g_sq[j];
    const float* row = g_A + (size_t)j * N0;
    float m = 0.0f;
    for (int i = t; i <= j; i += 256) {
        float d2 = sj + g_sq[i] - 2.0f * row[i];
        m = fmaxf(m, d2);
    }
    __shared__ float sm[256];
    sm[t] = m; __syncthreads();
    for (int s = 128; s > 0; s >>= 1) {
        if (t < s) sm[t] = fmaxf(sm[t], sm[t + s]);
        __syncthreads();
    }
    if (t == 0) atomicMax(&g_maxint, __float_as_int(fmaxf(sm[0], 0.0f)));
}

// ---------------- degree count per row (predicate on Gram, no dense A store) ----------------
__global__ void k_degree() {
    int j = blockIdx.x, t = threadIdx.x;
    float thr = 0.5f * __int_as_float(g_maxint);
    float sj = g_sq[j];
    const float* row = g_A + (size_t)j * N0;
    int cnt = 0;
    for (int i = t; i < j; i += 256)
        cnt += (sj + g_sq[i] - 2.0f * row[i] < thr) ? 1 : 0;
    __shared__ int sm[256];
    sm[t] = cnt; __syncthreads();
    for (int s = 128; s > 0; s >>= 1) {
        if (t < s) sm[t] += sm[t + s];
        __syncthreads();
    }
    if (t == 0) { g_deg[j] = sm[0]; g_dis[j] = rsqrtf(1.0f + (float)sm[0]); }
}

// ---------------- exclusive scan of degrees -> row pointers (single block) ----------------
__global__ __launch_bounds__(1024) void k_scan(const int* __restrict__ deg,
                                               int* __restrict__ rp, int n) {
    __shared__ int s[1024];
    int t = threadIdx.x;
    int base = t * 4;
    int v[4]; int local = 0;
#pragma unroll
    for (int q = 0; q < 4; q++) {
        int idx = base + q;
        v[q] = (idx < n) ? deg[idx] : 0;
        local += v[q];
    }
    s[t] = local; __syncthreads();
    for (int off = 1; off < 1024; off <<= 1) {
        int val = (t >= off) ? s[t - off] : 0;
        __syncthreads();
        s[t] += val;
        __syncthreads();
    }
    int run = (t == 0) ? 0 : s[t - 1];
#pragma unroll
    for (int q = 0; q < 4; q++) {
        int idx = base + q;
        if (idx < n) rp[idx] = run;
        run += v[q];
    }
    if (t == 1023) rp[n] = s[1023];
}

// ---------------- fill initial CSR: warp per row, ordered ballot compaction ----------------
__global__ void k_fillcsr(const int* __restrict__ rp, int* __restrict__ col, int Nl) {
    int w = (blockIdx.x * blockDim.x + threadIdx.x) >> 5;
    int lane = threadIdx.x & 31;
    if (w >= Nl) return;
    float thr = 0.5f * __int_as_float(g_maxint);
    float sj = g_sq[w];
    const float* row = g_A + (size_t)w * N0;
    int base = rp[w];
    for (int i0 = 0; i0 < w; i0 += 32) {
        int i = i0 + lane;
        bool pred = (i < w) && (sj + g_sq[i] - 2.0f * row[i] < thr);
        unsigned mask = __ballot_sync(0xFFFFFFFFu, pred);
        if (pred) col[base + __popc(mask & ((1u << lane) - 1u))] = i;
        base += __popc(mask);
    }
}

// ---------------- SpMM + GCN epilogue: xnew = relu(dis*(sum_nbr y + y) + b) ----------------
__global__ void k_spmm(const int* __restrict__ rp, const int* __restrict__ col,
                       const float* __restrict__ y, float* __restrict__ xnew,
                       const float* __restrict__ bias) {
    int j = blockIdx.x, t = threadIdx.x;  // 256 threads = H
    int p = rp[j], e = rp[j + 1];
    float acc = y[(size_t)j * H + t];     // self loop
    for (; p + 4 <= e; p += 4) {
        int c0 = col[p], c1 = col[p + 1], c2 = col[p + 2], c3 = col[p + 3];
        acc += y[(size_t)c0 * H + t] + y[(size_t)c1 * H + t]
             + y[(size_t)c2 * H + t] + y[(size_t)c3 * H + t];
    }
    for (; p < e; ++p) acc += y[(size_t)col[p] * H + t];
    xnew[(size_t)j * H + t] = fmaxf(g_dis[j] * acc + bias[t], 0.0f);
}

// ---------------- scorer matvecs: u = x@Wn, v = x@Wr ----------------
__global__ void k_scorevec(const float* __restrict__ x,
                           const float* __restrict__ Wn,
                           const float* __restrict__ Wr) {
    int j = blockIdx.x, t = threadIdx.x;  // 256 threads
    float p = x[(size_t)j * H + t];
    float uu = p * Wn[t], vv = p * Wr[t];
    __shared__ float su[256], sv[256];
    su[t] = uu; sv[t] = vv; __syncthreads();
    for (int s = 128; s > 0; s >>= 1) {
        if (t < s) { su[t] += su[t + s]; sv[t] += sv[t + s]; }
        __syncthreads();
    }
    if (t == 0) { g_u[j] = su[0]; g_v[j] = sv[0]; }
}

// ---------------- score = tanh(A@u + bs + v): warp per row over CSR ----------------
__global__ void k_auscore(const int* __restrict__ rp, const int* __restrict__ col,
                          const float* __restrict__ bsp, int Nl) {
    int w = (blockIdx.x * blockDim.x + threadIdx.x) >> 5;
    int lane = threadIdx.x & 31;
    if (w >= Nl) return;
    int s = rp[w], e = rp[w + 1];
    float acc = 0.0f;
    for (int p = s + lane; p < e; p += 32) acc += g_u[col[p]];
    for (int off = 16; off; off >>= 1) acc += __shfl_down_sync(0xFFFFFFFFu, acc, off);
    if (lane == 0) g_score[w] = tanhf(acc + bsp[0] + g_v[w]);
}

// ---------------- top-k via bitonic sort (1 block, 1024 threads, P=4096) ----------------
__device__ void bitonic4096(float* ss, int* si, bool byScore) {
    int t = threadIdx.x;
    for (int size = 2; size <= 4096; size <<= 1) {
        for (int stride = size >> 1; stride > 0; stride >>= 1) {
            __syncthreads();
            for (int p = t; p < 2048; p += 1024) {
                int i = ((p / stride) * (stride << 1)) + (p % stride);
                int j = i + stride;
                bool dirUp = ((i & size) == 0);
                float sa = ss[i], sb = ss[j];
                int ia = si[i], ib = si[j];
                bool b = byScore ? ((sb > sa) || (sb == sa && ib < ia)) : (ib < ia);
                if (b == dirUp) {
                    ss[i] = sb; ss[j] = sa;
                    si[i] = ib; si[j] = ia;
                }
            }
        }
    }
    __syncthreads();
}

__global__ __launch_bounds__(1024) void k_topk(int Nl, int k) {
    __shared__ float ss[4096];
    __shared__ int   si[4096];
    int t = threadIdx.x;
    for (int i = t; i < 4096; i += 1024) {
        if (i < Nl) { ss[i] = g_score[i]; si[i] = i; }
        else        { ss[i] = __int_as_float(0xff800000); si[i] = 0x7FFFFFFF; }
    }
    __syncthreads();
    bitonic4096(ss, si, true);   // descending by score (tie -> smaller index)
    for (int i = t; i < 4096; i += 1024)
        if (i >= k) si[i] = 0x7FFFFFFF;
    __syncthreads();
    bitonic4096(ss, si, false);  // selected k re-sorted ascending by index
    for (int r = t; r < k; r += 1024) { g_perm[r] = si[r]; g_vals[r] = ss[r]; }
}

// ---------------- gather x: xp[r] = x[perm[r]] * vals[r] ----------------
__global__ void k_gatherx(const float* __restrict__ xin, float* __restrict__ xout, int k) {
    int r = blockIdx.x, t = threadIdx.x;
    int pr = g_perm[r];
    float v = g_vals[r];
    xout[(size_t)r * H + t] = xin[(size_t)pr * H + t] * v;
}

// ---------------- inverse permutation ----------------
__global__ void k_invreset(int Nl) {
    int i = blockIdx.x * blockDim.x + threadIdx.x;
    if (i < Nl) g_inv[i] = -1;
}
__global__ void k_invset(int k) {
    int r = blockIdx.x * blockDim.x + threadIdx.x;
    if (r < k) g_inv[g_perm[r]] = r;
}

// ---------------- pooled CSR: count surviving neighbors per pooled row ----------------
__global__ void k_deg2(const int* __restrict__ rpIn, const int* __restrict__ colIn, int k) {
    int w = (blockIdx.x * blockDim.x + threadIdx.x) >> 5;
    int lane = threadIdx.x & 31;
    if (w >= k) return;
    int pr = g_perm[w];
    int s = rpIn[pr], e = rpIn[pr + 1];
    int cnt = 0;
    for (int p = s + lane; p < e; p += 32) cnt += (g_inv[colIn[p]] >= 0) ? 1 : 0;
    for (int off = 16; off; off >>= 1) cnt += __shfl_down_sync(0xFFFFFFFFu, cnt, off);
    if (lane == 0) { g_deg[w] = cnt; g_dis[w] = rsqrtf(1.0f + (float)cnt); }
}

// ---------------- pooled CSR: fill (ordered; ascending old -> ascending new) ----------------
__global__ void k_fill2(const int* __restrict__ rpIn, const int* __restrict__ colIn,
                        const int* __restrict__ rpOut, int* __restrict__ colOut, int k) {
    int w = (blockIdx.x * blockDim.x + threadIdx.x) >> 5;
    int lane = threadIdx.x & 31;
    if (w >= k) return;
    int pr = g_perm[w];
    int s = rpIn[pr], e = rpIn[pr + 1];
    int base = rpOut[w];
    for (int p0 = s; p0 < e; p0 += 32) {
        int p = p0 + lane;
        int m = -1;
        bool pred = false;
        if (p < e) { m = g_inv[colIn[p]]; pred = (m >= 0); }
        unsigned mask = __ballot_sync(0xFFFFFFFFu, pred);
        if (pred) colOut[base + __popc(mask & ((1u << lane) - 1u))] = m;
        base += __popc(mask);
    }
}

// ---------------- readout: column max + sum -> accumulate into out ----------------
__global__ void k_readout_part(const float* __restrict__ x, int k) {
    int b = blockIdx.x, t = threadIdx.x;  // grid 32, 256 threads
    float mx = __int_as_float(0xff800000), sm = 0.0f;
    for (int r = b; r < k; r += 32) {
        float v = x[(size_t)r * H + t];
        mx = fmaxf(mx, v);
        sm += v;
    }
    g_part[b * 512 + t] = mx;
    g_part[b * 512 + 256 + t] = sm;
}

__global__ void k_readout_final(float* out, float invk) {
    int t = threadIdx.x;  // 256
    float mx = __int_as_float(0xff800000), sm = 0.0f;
    for (int b = 0; b < 32; b++) {
        mx = fmaxf(mx, g_part[b * 512 + t]);
        sm += g_part[b * 512 + 256 + t];
    }
    out[t] += mx;
    out[256 + t] += sm * invk;
}

// ---------------- one GCN + SAGPool + readout layer (CSR adjacency) ----------------
static void run_layer(const float* xin, int Kin, const int* rpIn, const int* colIn, int Nl,
                      const float* W, const float* bvec,
                      const float* Wr, const float* Wn, const float* bs,
                      int k, float* xnew, float* xpool,
                      int* rpOut, int* colOut, int* pdeg,
                      float* ybuf, const float* pdis, float* d_out)
{
    // y = dis .* (x @ W)
    {
        dim3 g(H / 128, Nl / 128);
        k_sgemm<1, false, false><<<g, 256>>>(xin, W, ybuf, Nl, H, Kin, pdis);
    }
    // xnew = relu(dis .* (A@y + y) + b)  via CSR SpMM
    k_spmm<<<Nl, 256>>>(rpIn, colIn, ybuf, xnew, bvec);
    k_scorevec<<<Nl, 256>>>(xnew, Wn, Wr);
    k_auscore<<<(Nl + 7) / 8, 256>>>(rpIn, colIn, bs, Nl);
    k_topk<<<1, 1024>>>(Nl, k);
    k_gatherx<<<k, 256>>>(xnew, xpool, k);
    // pooled CSR
    k_invreset<<<(Nl + 255) / 256, 256>>>(Nl);
    k_invset<<<(k + 255) / 256, 256>>>(k);
    k_deg2<<<(k + 7) / 8, 256>>>(rpIn, colIn, k);
    k_scan<<<1, 1024>>>(pdeg, rpOut, k);
    k_fill2<<<(k + 7) / 8, 256>>>(rpIn, colIn, rpOut, colOut, k);
    // readout accumulate
    k_readout_part<<<32, 256>>>(xpool, k);
    k_readout_final<<<1, 256>>>(d_out, 1.0f / (float)k);
}

extern "C" void kernel_launch(void* const* d_in, const int* in_sizes, int n_in,
                              void* d_out, int out_size) {
    const float* feature = (const float*)d_in[0];
    const float* img     = (const float*)d_in[1];
    const float* W_pos   = (const float*)d_in[2];
    const float* b_pos   = (const float*)d_in[3];
    const float* W1 = (const float*)d_in[4];  const float* b1 = (const float*)d_in[5];
    const float* W2 = (const float*)d_in[6];  const float* b2 = (const float*)d_in[7];
    const float* W3 = (const float*)d_in[8];  const float* b3 = (const float*)d_in[9];
    const float* Wr1 = (const float*)d_in[10]; const float* Wn1 = (const float*)d_in[11];
    const float* bs1 = (const float*)d_in[12];
    const float* Wr2 = (const float*)d_in[13]; const float* Wn2 = (const float*)d_in[14];
    const float* bs2 = (const float*)d_in[15];
    const float* Wr3 = (const float*)d_in[16]; const float* Wn3 = (const float*)d_in[17];
    const float* bs3 = (const float*)d_in[18];
    float* out = (float*)d_out;

    float *pfeat, *pA, *px, *px2, *py, *pdis;
    int *pcolA, *pcolB, *prpA, *prpB, *pdeg;
    cudaGetSymbolAddress((void**)&pfeat, g_feat);
    cudaGetSymbolAddress((void**)&pA,    g_A);
    cudaGetSymbolAddress((void**)&px,    g_x);
    cudaGetSymbolAddress((void**)&px2,   g_x2);
    cudaGetSymbolAddress((void**)&py,    g_y);
    cudaGetSymbolAddress((void**)&pdis,  g_dis);
    cudaGetSymbolAddress((void**)&pcolA, g_colA);
    cudaGetSymbolAddress((void**)&pcolB, g_colB);
    cudaGetSymbolAddress((void**)&prpA,  g_rpA);
    cudaGetSymbolAddress((void**)&prpB,  g_rpB);
    cudaGetSymbolAddress((void**)&pdeg,  g_deg);

    k_init<<<2, 256>>>(out);
    k_posconcat<<<N0, 128>>>(feature, img, W_pos, b_pos);

    // Gram (lower triangle + diagonal blocks): G = feat @ feat^T into g_A
    {
        dim3 g(N0 / 128, N0 / 128);
        k_sgemm<0, true, true><<<g, 256>>>(pfeat, pfeat, pA, N0, N0, F0, nullptr);
    }
    k_diag<<<N0 / 256, 256>>>();
    k_maxd2<<<N0, 256>>>();
    // adjacency directly to CSR (Gram read twice, never overwritten)
    k_degree<<<N0, 256>>>();
    k_scan<<<1, 1024>>>(pdeg, prpA, N0);
    k_fillcsr<<<N0 / 8, 256>>>(prpA, pcolA, N0);

    // layer 1: CSR A (4096) -> pooled CSR B (3072)
    run_layer(pfeat, F0, prpA, pcolA, N0,  W1, b1, Wr1, Wn1, bs1, KP1,
              px, px2, prpB, pcolB, pdeg, py, pdis, out);
    // layer 2: CSR B (3072) -> pooled CSR A (2304)
    run_layer(px2, H, prpB, pcolB, KP1, W2, b2, Wr2, Wn2, bs2, KP2,
              px, px2, prpA, pcolA, pdeg, py, pdis, out);
    // layer 3: CSR A (2304) -> pooled CSR B (1728)
    run_layer(px2, H, prpA, pcolA, KP2, W3, b3, Wr3, Wn3, bs3, KP3,
              px, px2, prpB, pcolB, pdeg, py, pdis, out);
}

// round 16
// speedup vs baseline: 3.5577x; 1.3055x over previous
#include <cuda_runtime.h>
#include <cuda_bf16.h>
#include <math.h>
#include <stdint.h>

#define N0 4096
#define F0 512
#define H  256
#define KP1 3072
#define KP2 2304
#define KP3 1728
#define MAXE (N0*(N0-1)/2)   // 8,386,560 max strictly-lower edges

// ---------------- device scratch (static globals: no runtime allocation) ----------------
__device__ __align__(256) float g_feat[N0 * F0];
__device__ __align__(256) __nv_bfloat16 g_featH[N0 * F0];
__device__ __align__(256) __nv_bfloat16 g_featL[N0 * F0];
__device__ __align__(256) float g_A [(size_t)N0 * N0];   // Gram matrix (lower tri valid)
__device__ __align__(256) float g_x [N0 * H];
__device__ __align__(256) float g_x2[N0 * H];
__device__ __align__(256) float g_y [N0 * H];
__device__ float g_sq[N0];
__device__ float g_dis[N0];
__device__ float g_u[N0];
__device__ float g_v[N0];
__device__ float g_score[N0];
__device__ int   g_perm[N0];
__device__ float g_vals[N0];
__device__ int   g_maxint;
__device__ float g_part[32 * 512];
// CSR adjacency (double-buffered across layers)
__device__ int g_colA[MAXE];
__device__ int g_colB[MAXE];
__device__ int g_rpA[N0 + 1];
__device__ int g_rpB[N0 + 1];
__device__ int g_deg[N0];
__device__ int g_inv[N0];

// ---------------- init ----------------
__global__ void k_init(float* out) {
    int t = blockIdx.x * blockDim.x + threadIdx.x;
    if (t < 512) out[t] = 0.0f;
    if (t == 0) g_maxint = 0;
}

// ---------------- pos MLP + concat -> feat [N0, 512] ----------------
__global__ void k_posconcat(const float* __restrict__ feature,
                            const float* __restrict__ img,
                            const float* __restrict__ Wp,
                            const float* __restrict__ bp) {
    int n = blockIdx.x;
    int t = threadIdx.x;  // 128 threads
    const float* fr = feature + (size_t)n * 500;
    float* dst = g_feat + (size_t)n * F0;
    for (int i = t; i < 500; i += 128) dst[i] = fr[i];
    if (t < 12) {
        float s = bp[t];
#pragma unroll
        for (int h = 0; h < 6; h++) s += img[n * 6 + h] * Wp[h * 12 + t];
        dst[500 + t] = fmaxf(s, 0.0f);
    }
}

// ---------------- split feat into bf16 hi/lo limbs ----------------
__global__ void k_split() {
    int i = blockIdx.x * blockDim.x + threadIdx.x;  // grid covers N0*F0
    float x = g_feat[i];
    __nv_bfloat16 h = __float2bfloat16(x);
    g_featH[i] = h;
    g_featL[i] = __float2bfloat16(x - __bfloat162float(h));
}

// ---------------- exact squared norms in fp32 ----------------
__global__ void k_sqnorm() {
    int j = blockIdx.x, t = threadIdx.x;  // 128 threads
    const float* row = g_feat + (size_t)j * F0;
    float s = 0.0f;
    for (int i = t; i < F0; i += 128) { float v = row[i]; s = fmaf(v, v, s); }
    __shared__ float sm[128];
    sm[t] = s; __syncthreads();
    for (int st = 64; st > 0; st >>= 1) {
        if (t < st) sm[t] += sm[t + st];
        __syncthreads();
    }
    if (t == 0) g_sq[j] = sm[0];
}

// ================= Gram via mma.sync bf16 (2-limb split, 3 products) =================
// C[128x128] per block; 8 warps in 4(M) x 2(N); warp tile 32x64.
// SMEM rows: 64 bf16 = 128B; granule (16B) swizzled: phys = g ^ (row&7).
__device__ __forceinline__ void ldmA4(uint32_t f[4], uint32_t base, int R, int g, int lane) {
    int lgrp = lane >> 3, lrow = lane & 7;
    int r = R + lrow + ((lgrp & 1) << 3);
    int gg = g + (lgrp >> 1);
    uint32_t addr = base + (r << 7) + ((gg ^ (r & 7)) << 4);
    asm volatile("ldmatrix.sync.aligned.m8n8.x4.shared.b16 {%0,%1,%2,%3}, [%4];"
        : "=r"(f[0]), "=r"(f[1]), "=r"(f[2]), "=r"(f[3]) : "r"(addr));
}
__device__ __forceinline__ void ldmB4(uint32_t f0[2], uint32_t f1[2],
                                      uint32_t base, int Nb, int g, int lane) {
    int lgrp = lane >> 3, lrow = lane & 7;
    int r = Nb + lrow + ((lgrp >> 1) << 3);
    int gg = g + (lgrp & 1);
    uint32_t addr = base + (r << 7) + ((gg ^ (r & 7)) << 4);
    uint32_t r0, r1, r2, r3;
    asm volatile("ldmatrix.sync.aligned.m8n8.x4.shared.b16 {%0,%1,%2,%3}, [%4];"
        : "=r"(r0), "=r"(r1), "=r"(r2), "=r"(r3) : "r"(addr));
    f0[0] = r0; f0[1] = r1; f1[0] = r2; f1[1] = r3;
}
__device__ __forceinline__ void mma16816(float c[4], const uint32_t a[4], const uint32_t b[2]) {
    asm volatile(
        "mma.sync.aligned.m16n8k16.row.col.f32.bf16.bf16.f32 "
        "{%0,%1,%2,%3}, {%4,%5,%6,%7}, {%8,%9}, {%0,%1,%2,%3};"
        : "+f"(c[0]), "+f"(c[1]), "+f"(c[2]), "+f"(c[3])
        : "r"(a[0]), "r"(a[1]), "r"(a[2]), "r"(a[3]), "r"(b[0]), "r"(b[1]));
}

__global__ __launch_bounds__(256) void k_gram_mma(float* __restrict__ C) {
    int bx = blockIdx.x, by = blockIdx.y;
    if (bx > by) return;                 // lower triangle blocks only
    int m0 = by * 128, n0 = bx * 128;

    __shared__ __align__(16) __nv_bfloat16 sA[128 * 64];
    __shared__ __align__(16) __nv_bfloat16 sB[128 * 64];
    uint32_t sAu = (uint32_t)__cvta_generic_to_shared(sA);
    uint32_t sBu = (uint32_t)__cvta_generic_to_shared(sB);

    int tid = threadIdx.x;
    int wid = tid >> 5, lane = tid & 31;
    int wm0 = (wid & 3) * 32;            // warp M offset
    int wn0 = (wid >> 2) * 64;           // warp N offset

    float c[2][8][4];
#pragma unroll
    for (int mf = 0; mf < 2; mf++)
#pragma unroll
        for (int nf = 0; nf < 8; nf++)
#pragma unroll
            for (int q = 0; q < 4; q++) c[mf][nf][q] = 0.0f;

    for (int k0 = 0; k0 < F0; k0 += 32) {
        // stage A/B tiles: hi limb at granules 0-3 (k0..k0+31), lo at 4-7
#pragma unroll
        for (int i = tid; i < 1024; i += 256) {
            int r = i >> 3, g = i & 7;
            const uint4* srcA;
            const uint4* srcB;
            if (g < 4) {
                srcA = (const uint4*)(g_featH + (size_t)(m0 + r) * F0 + k0 + g * 8);
                srcB = (const uint4*)(g_featH + (size_t)(n0 + r) * F0 + k0 + g * 8);
            } else {
                srcA = (const uint4*)(g_featL + (size_t)(m0 + r) * F0 + k0 + (g - 4) * 8);
                srcB = (const uint4*)(g_featL + (size_t)(n0 + r) * F0 + k0 + (g - 4) * 8);
            }
            *(uint4*)(sA + r * 64 + ((g ^ (r & 7)) << 3)) = *srcA;
            *(uint4*)(sB + r * 64 + ((g ^ (r & 7)) << 3)) = *srcB;
        }
        __syncthreads();

#pragma unroll
        for (int s = 0; s < 2; s++) {    // two k16 steps per 32-chunk
            int gh = s * 2, gl = 4 + s * 2;
            uint32_t ah[2][4], al[2][4];
            ldmA4(ah[0], sAu, wm0,      gh, lane);
            ldmA4(ah[1], sAu, wm0 + 16, gh, lane);
            ldmA4(al[0], sAu, wm0,      gl, lane);
            ldmA4(al[1], sAu, wm0 + 16, gl, lane);
            uint32_t bh[8][2], bl[8][2];
#pragma unroll
            for (int n2 = 0; n2 < 4; n2++) {
                ldmB4(bh[2 * n2], bh[2 * n2 + 1], sBu, wn0 + n2 * 16, gh, lane);
                ldmB4(bl[2 * n2], bl[2 * n2 + 1], sBu, wn0 + n2 * 16, gl, lane);
            }
#pragma unroll
            for (int mf = 0; mf < 2; mf++)
#pragma unroll
                for (int nf = 0; nf < 8; nf++) {
                    mma16816(c[mf][nf], ah[mf], bh[nf]);  // hi*hi
                    mma16816(c[mf][nf], ah[mf], bl[nf]);  // hi*lo
                    mma16816(c[mf][nf], al[mf], bh[nf]);  // lo*hi
                }
        }
        __syncthreads();
    }

    // epilogue: c0,c1 -> (row, col..col+1); c2,c3 -> (row+8, ..)
    int rbase = m0 + wm0 + (lane >> 2);
    int cbase = n0 + wn0 + ((lane & 3) << 1);
#pragma unroll
    for (int mf = 0; mf < 2; mf++)
#pragma unroll
        for (int nf = 0; nf < 8; nf++) {
            int r = rbase + mf * 16, cc = cbase + nf * 8;
            *(float2*)&C[(size_t)r * N0 + cc]       = make_float2(c[mf][nf][0], c[mf][nf][1]);
            *(float2*)&C[(size_t)(r + 8) * N0 + cc] = make_float2(c[mf][nf][2], c[mf][nf][3]);
        }
}

// ---------------- skinny SGEMM 64x64 tile: C = dis[m] * (A[M,K] @ B[K,N]) ----------------
__global__ __launch_bounds__(256) void k_sgemm64(
    const float* __restrict__ A, const float* __restrict__ B, float* __restrict__ C,
    int M, int N, int K, const float* __restrict__ dis)
{
    __shared__ float As[16][68];
    __shared__ float Bs[16][68];
    int tid = threadIdx.x;
    int m0 = blockIdx.y * 64, n0 = blockIdx.x * 64;
    int tx = tid & 15, ty = tid >> 4;
    float acc[4][4];
#pragma unroll
    for (int i = 0; i < 4; i++)
#pragma unroll
        for (int j = 0; j < 4; j++) acc[i][j] = 0.0f;

    int arow = tid >> 2, akc = (tid & 3) * 4;
    int brow = tid >> 4, bc = (tid & 15) * 4;

    for (int k0 = 0; k0 < K; k0 += 16) {
        float4 av = *(const float4*)(A + (size_t)(m0 + arow) * K + k0 + akc);
        As[akc + 0][arow] = av.x; As[akc + 1][arow] = av.y;
        As[akc + 2][arow] = av.z; As[akc + 3][arow] = av.w;
        float4 bv = *(const float4*)(B + (size_t)(k0 + brow) * N + n0 + bc);
        *(float4*)&Bs[brow][bc] = bv;
        __syncthreads();
#pragma unroll
        for (int kk = 0; kk < 16; kk++) {
            float a[4], b[4];
#pragma unroll
            for (int i = 0; i < 4; i++) a[i] = As[kk][ty * 4 + i];
#pragma unroll
            for (int j = 0; j < 4; j++) b[j] = Bs[kk][tx * 4 + j];
#pragma unroll
            for (int i = 0; i < 4; i++)
#pragma unroll
                for (int j = 0; j < 4; j++)
                    acc[i][j] = fmaf(a[i], b[j], acc[i][j]);
        }
        __syncthreads();
    }
#pragma unroll
    for (int i = 0; i < 4; i++) {
        int m = m0 + ty * 4 + i;
        float d = dis[m];
#pragma unroll
        for (int j = 0; j < 4; j++)
            C[(size_t)m * N + n0 + tx * 4 + j] = d * acc[i][j];
    }
}

// ---------------- max d2 over lower triangle ----------------
__global__ void k_maxd2() {
    int j = blockIdx.x, t = threadIdx.x;
    float sj = g_sq[j];
    const float* row = g_A + (size_t)j * N0;
    float m = 0.0f;
    for (int i = t; i <= j; i += 256) {
        float d2 = sj + g_sq[i] - 2.0f * row[i];
        m = fmaxf(m, d2);
    }
    __shared__ float sm[256];
    sm[t] = m; __syncthreads();
    for (int s = 128; s > 0; s >>= 1) {
        if (t < s) sm[t] = fmaxf(sm[t], sm[t + s]);
        __syncthreads();
    }
    if (t == 0) atomicMax(&g_maxint, __float_as_int(fmaxf(sm[0], 0.0f)));
}

// ---------------- degree count per row (predicate on Gram, no dense A store) ----------------
__global__ void k_degree() {
    int j = blockIdx.x, t = threadIdx.x;
    float thr = 0.5f * __int_as_float(g_maxint);
    float sj = g_sq[j];
    const float* row = g_A + (size_t)j * N0;
    int cnt = 0;
    for (int i = t; i < j; i += 256)
        cnt += (sj + g_sq[i] - 2.0f * row[i] < thr) ? 1 : 0;
    __shared__ int sm[256];
    sm[t] = cnt; __syncthreads();
    for (int s = 128; s > 0; s >>= 1) {
        if (t < s) sm[t] += sm[t + s];
        __syncthreads();
    }
    if (t == 0) { g_deg[j] = sm[0]; g_dis[j] = rsqrtf(1.0f + (float)sm[0]); }
}

// ---------------- exclusive scan of degrees -> row pointers (single block) ----------------
__global__ __launch_bounds__(1024) void k_scan(const int* __restrict__ deg,
                                               int* __restrict__ rp, int n) {
    __shared__ int s[1024];
    int t = threadIdx.x;
    int base = t * 4;
    int v[4]; int local = 0;
#pragma unroll
    for (int q = 0; q < 4; q++) {
        int idx = base + q;
        v[q] = (idx < n) ? deg[idx] : 0;
        local += v[q];
    }
    s[t] = local; __syncthreads();
    for (int off = 1; off < 1024; off <<= 1) {
        int val = (t >= off) ? s[t - off] : 0;
        __syncthreads();
        s[t] += val;
        __syncthreads();
    }
    int run = (t == 0) ? 0 : s[t - 1];
#pragma unroll
    for (int q = 0; q < 4; q++) {
        int idx = base + q;
        if (idx < n) rp[idx] = run;
        run += v[q];
    }
    if (t == 1023) rp[n] = s[1023];
}

// ---------------- fill initial CSR: warp per row, ordered ballot compaction ----------------
__global__ void k_fillcsr(const int* __restrict__ rp, int* __restrict__ col, int Nl) {
    int w = (blockIdx.x * blockDim.x + threadIdx.x) >> 5;
    int lane = threadIdx.x & 31;
    if (w >= Nl) return;
    float thr = 0.5f * __int_as_float(g_maxint);
    float sj = g_sq[w];
    const float* row = g_A + (size_t)w * N0;
    int base = rp[w];
    for (int i0 = 0; i0 < w; i0 += 32) {
        int i = i0 + lane;
        bool pred = (i < w) && (sj + g_sq[i] - 2.0f * row[i] < thr);
        unsigned mask = __ballot_sync(0xFFFFFFFFu, pred);
        if (pred) col[base + __popc(mask & ((1u << lane) - 1u))] = i;
        base += __popc(mask);
    }
}

// ---------------- SpMM + GCN epilogue: xnew = relu(dis*(sum_nbr y + y) + b) ----------------
__global__ void k_spmm(const int* __restrict__ rp, const int* __restrict__ col,
                       const float* __restrict__ y, float* __restrict__ xnew,
                       const float* __restrict__ bias) {
    int j = blockIdx.x, t = threadIdx.x;  // 256 threads = H
    int p = rp[j], e = rp[j + 1];
    float acc = y[(size_t)j * H + t];     // self loop
    for (; p + 4 <= e; p += 4) {
        int c0 = col[p], c1 = col[p + 1], c2 = col[p + 2], c3 = col[p + 3];
        acc += y[(size_t)c0 * H + t] + y[(size_t)c1 * H + t]
             + y[(size_t)c2 * H + t] + y[(size_t)c3 * H + t];
    }
    for (; p < e; ++p) acc += y[(size_t)col[p] * H + t];
    xnew[(size_t)j * H + t] = fmaxf(g_dis[j] * acc + bias[t], 0.0f);
}

// ---------------- scorer matvecs: u = x@Wn, v = x@Wr ----------------
__global__ void k_scorevec(const float* __restrict__ x,
                           const float* __restrict__ Wn,
                           const float* __restrict__ Wr) {
    int j = blockIdx.x, t = threadIdx.x;  // 256 threads
    float p = x[(size_t)j * H + t];
    float uu = p * Wn[t], vv = p * Wr[t];
    __shared__ float su[256], sv[256];
    su[t] = uu; sv[t] = vv; __syncthreads();
    for (int s = 128; s > 0; s >>= 1) {
        if (t < s) { su[t] += su[t + s]; sv[t] += sv[t + s]; }
        __syncthreads();
    }
    if (t == 0) { g_u[j] = su[0]; g_v[j] = sv[0]; }
}

// ---------------- score = tanh(A@u + bs + v): warp per row over CSR ----------------
__global__ void k_auscore(const int* __restrict__ rp, const int* __restrict__ col,
                          const float* __restrict__ bsp, int Nl) {
    int w = (blockIdx.x * blockDim.x + threadIdx.x) >> 5;
    int lane = threadIdx.x & 31;
    if (w >= Nl) return;
    int s = rp[w], e = rp[w + 1];
    float acc = 0.0f;
    for (int p = s + lane; p < e; p += 32) acc += g_u[col[p]];
    for (int off = 16; off; off >>= 1) acc += __shfl_down_sync(0xFFFFFFFFu, acc, off);
    if (lane == 0) g_score[w] = tanhf(acc + bsp[0] + g_v[w]);
}

// ---------------- top-k via bitonic sort (1 block, 1024 threads, P=4096) ----------------
__device__ void bitonic4096(float* ss, int* si, bool byScore) {
    int t = threadIdx.x;
    for (int size = 2; size <= 4096; size <<= 1) {
        for (int stride = size >> 1; stride > 0; stride >>= 1) {
            __syncthreads();
            for (int p = t; p < 2048; p += 1024) {
                int i = ((p / stride) * (stride << 1)) + (p % stride);
                int j = i + stride;
                bool dirUp = ((i & size) == 0);
                float sa = ss[i], sb = ss[j];
                int ia = si[i], ib = si[j];
                bool b = byScore ? ((sb > sa) || (sb == sa && ib < ia)) : (ib < ia);
                if (b == dirUp) {
                    ss[i] = sb; ss[j] = sa;
                    si[i] = ib; si[j] = ia;
                }
            }
        }
    }
    __syncthreads();
}

__global__ __launch_bounds__(1024) void k_topk(int Nl, int k) {
    __shared__ float ss[4096];
    __shared__ int   si[4096];
    int t = threadIdx.x;
    for (int i = t; i < 4096; i += 1024) {
        if (i < Nl) { ss[i] = g_score[i]; si[i] = i; }
        else        { ss[i] = __int_as_float(0xff800000); si[i] = 0x7FFFFFFF; }
    }
    __syncthreads();
    bitonic4096(ss, si, true);   // descending by score (tie -> smaller index)
    for (int i = t; i < 4096; i += 1024)
        if (i >= k) si[i] = 0x7FFFFFFF;
    __syncthreads();
    bitonic4096(ss, si, false);  // selected k re-sorted ascending by index
    for (int r = t; r < k; r += 1024) { g_perm[r] = si[r]; g_vals[r] = ss[r]; }
}

// ---------------- gather x: xp[r] = x[perm[r]] * vals[r] ----------------
__global__ void k_gatherx(const float* __restrict__ xin, float* __restrict__ xout, int k) {
    int r = blockIdx.x, t = threadIdx.x;
    int pr = g_perm[r];
    float v = g_vals[r];
    xout[(size_t)r * H + t] = xin[(size_t)pr * H + t] * v;
}

// ---------------- inverse permutation ----------------
__global__ void k_invreset(int Nl) {
    int i = blockIdx.x * blockDim.x + threadIdx.x;
    if (i < Nl) g_inv[i] = -1;
}
__global__ void k_invset(int k) {
    int r = blockIdx.x * blockDim.x + threadIdx.x;
    if (r < k) g_inv[g_perm[r]] = r;
}

// ---------------- pooled CSR: count surviving neighbors per pooled row ----------------
__global__ void k_deg2(const int* __restrict__ rpIn, const int* __restrict__ colIn, int k) {
    int w = (blockIdx.x * blockDim.x + threadIdx.x) >> 5;
    int lane = threadIdx.x & 31;
    if (w >= k) return;
    int pr = g_perm[w];
    int s = rpIn[pr], e = rpIn[pr + 1];
    int cnt = 0;
    for (int p = s + lane; p < e; p += 32) cnt += (g_inv[colIn[p]] >= 0) ? 1 : 0;
    for (int off = 16; off; off >>= 1) cnt += __shfl_down_sync(0xFFFFFFFFu, cnt, off);
    if (lane == 0) { g_deg[w] = cnt; g_dis[w] = rsqrtf(1.0f + (float)cnt); }
}

// ---------------- pooled CSR: fill (ordered; ascending old -> ascending new) ----------------
__global__ void k_fill2(const int* __restrict__ rpIn, const int* __restrict__ colIn,
                        const int* __restrict__ rpOut, int* __restrict__ colOut, int k) {
    int w = (blockIdx.x * blockDim.x + threadIdx.x) >> 5;
    int lane = threadIdx.x & 31;
    if (w >= k) return;
    int pr = g_perm[w];
    int s = rpIn[pr], e = rpIn[pr + 1];
    int base = rpOut[w];
    for (int p0 = s; p0 < e; p0 += 32) {
        int p = p0 + lane;
        int m = -1;
        bool pred = false;
        if (p < e) { m = g_inv[colIn[p]]; pred = (m >= 0); }
        unsigned mask = __ballot_sync(0xFFFFFFFFu, pred);
        if (pred) colOut[base + __popc(mask & ((1u << lane) - 1u))] = m;
        base += __popc(mask);
    }
}

// ---------------- readout: column max + sum -> accumulate into out ----------------
__global__ void k_readout_part(const float* __restrict__ x, int k) {
    int b = blockIdx.x, t = threadIdx.x;  // grid 32, 256 threads
    float mx = __int_as_float(0xff800000), sm = 0.0f;
    for (int r = b; r < k; r += 32) {
        float v = x[(size_t)r * H + t];
        mx = fmaxf(mx, v);
        sm += v;
    }
    g_part[b * 512 + t] = mx;
    g_part[b * 512 + 256 + t] = sm;
}

__global__ void k_readout_final(float* out, float invk) {
    int t = threadIdx.x;  // 256
    float mx = __int_as_float(0xff800000), sm = 0.0f;
    for (int b = 0; b < 32; b++) {
        mx = fmaxf(mx, g_part[b * 512 + t]);
        sm += g_part[b * 512 + 256 + t];
    }
    out[t] += mx;
    out[256 + t] += sm * invk;
}

// ---------------- one GCN + SAGPool + readout layer (CSR adjacency) ----------------
static void run_layer(const float* xin, int Kin, const int* rpIn, const int* colIn, int Nl,
                      const float* W, const float* bvec,
                      const float* Wr, const float* Wn, const float* bs,
                      int k, float* xnew, float* xpool,
                      int* rpOut, int* colOut, int* pdeg,
                      float* ybuf, const float* pdis, float* d_out)
{
    // y = dis .* (x @ W)  -- 64x64 tiles for occupancy
    {
        dim3 g(H / 64, Nl / 64);
        k_sgemm64<<<g, 256>>>(xin, W, ybuf, Nl, H, Kin, pdis);
    }
    // xnew = relu(dis .* (A@y + y) + b)  via CSR SpMM
    k_spmm<<<Nl, 256>>>(rpIn, colIn, ybuf, xnew, bvec);
    k_scorevec<<<Nl, 256>>>(xnew, Wn, Wr);
    k_auscore<<<(Nl + 7) / 8, 256>>>(rpIn, colIn, bs, Nl);
    k_topk<<<1, 1024>>>(Nl, k);
    k_gatherx<<<k, 256>>>(xnew, xpool, k);
    // pooled CSR
    k_invreset<<<(Nl + 255) / 256, 256>>>(Nl);
    k_invset<<<(k + 255) / 256, 256>>>(k);
    k_deg2<<<(k + 7) / 8, 256>>>(rpIn, colIn, k);
    k_scan<<<1, 1024>>>(pdeg, rpOut, k);
    k_fill2<<<(k + 7) / 8, 256>>>(rpIn, colIn, rpOut, colOut, k);
    // readout accumulate
    k_readout_part<<<32, 256>>>(xpool, k);
    k_readout_final<<<1, 256>>>(d_out, 1.0f / (float)k);
}

extern "C" void kernel_launch(void* const* d_in, const int* in_sizes, int n_in,
                              void* d_out, int out_size) {
    const float* feature = (const float*)d_in[0];
    const float* img     = (const float*)d_in[1];
    const float* W_pos   = (const float*)d_in[2];
    const float* b_pos   = (const float*)d_in[3];
    const float* W1 = (const float*)d_in[4];  const float* b1 = (const float*)d_in[5];
    const float* W2 = (const float*)d_in[6];  const float* b2 = (const float*)d_in[7];
    const float* W3 = (const float*)d_in[8];  const float* b3 = (const float*)d_in[9];
    const float* Wr1 = (const float*)d_in[10]; const float* Wn1 = (const float*)d_in[11];
    const float* bs1 = (const float*)d_in[12];
    const float* Wr2 = (const float*)d_in[13]; const float* Wn2 = (const float*)d_in[14];
    const float* bs2 = (const float*)d_in[15];
    const float* Wr3 = (const float*)d_in[16]; const float* Wn3 = (const float*)d_in[17];
    const float* bs3 = (const float*)d_in[18];
    float* out = (float*)d_out;

    float *pfeat, *pA, *px, *px2, *py, *pdis;
    int *pcolA, *pcolB, *prpA, *prpB, *pdeg;
    cudaGetSymbolAddress((void**)&pfeat, g_feat);
    cudaGetSymbolAddress((void**)&pA,    g_A);
    cudaGetSymbolAddress((void**)&px,    g_x);
    cudaGetSymbolAddress((void**)&px2,   g_x2);
    cudaGetSymbolAddress((void**)&py,    g_y);
    cudaGetSymbolAddress((void**)&pdis,  g_dis);
    cudaGetSymbolAddress((void**)&pcolA, g_colA);
    cudaGetSymbolAddress((void**)&pcolB, g_colB);
    cudaGetSymbolAddress((void**)&prpA,  g_rpA);
    cudaGetSymbolAddress((void**)&prpB,  g_rpB);
    cudaGetSymbolAddress((void**)&pdeg,  g_deg);

    k_init<<<2, 256>>>(out);
    k_posconcat<<<N0, 128>>>(feature, img, W_pos, b_pos);
    k_split<<<(N0 * F0) / 256, 256>>>();
    k_sqnorm<<<N0, 128>>>();

    // Gram lower triangle via bf16 2-limb tensor-core MMA
    {
        dim3 g(N0 / 128, N0 / 128);
        k_gram_mma<<<g, 256>>>(pA);
    }
    k_maxd2<<<N0, 256>>>();
    // adjacency directly to CSR (Gram read twice, never overwritten)
    k_degree<<<N0, 256>>>();
    k_scan<<<1, 1024>>>(pdeg, prpA, N0);
    k_fillcsr<<<N0 / 8, 256>>>(prpA, pcolA, N0);

    // layer 1: CSR A (4096) -> pooled CSR B (3072)
    run_layer(pfeat, F0, prpA, pcolA, N0,  W1, b1, Wr1, Wn1, bs1, KP1,
              px, px2, prpB, pcolB, pdeg, py, pdis, out);
    // layer 2: CSR B (3072) -> pooled CSR A (2304)
    run_layer(px2, H, prpB, pcolB, KP1, W2, b2, Wr2, Wn2, bs2, KP2,
              px, px2, prpA, pcolA, pdeg, py, pdis, out);
    // layer 3: CSR A (2304) -> pooled CSR B (1728)
    run_layer(px2, H, prpA, pcolA, KP2, W3, b3, Wr3, Wn3, bs3, KP3,
              px, px2, prpB, pcolB, pdeg, py, pdis, out);
}

// round 17
// speedup vs baseline: 5.2699x; 1.4813x over previous
#include <cuda_runtime.h>
#include <cuda_bf16.h>
#include <math.h>
#include <stdint.h>

#define N0 4096
#define F0 512
#define H  256
#define KP1 3072
#define KP2 2304
#define KP3 1728
#define MAXE (N0*(N0-1)/2)   // 8,386,560 max strictly-lower edges

// ---------------- device scratch (static globals: no runtime allocation) ----------------
__device__ __align__(256) float g_feat[N0 * F0];
__device__ __align__(256) __nv_bfloat16 g_featH[N0 * F0];
__device__ __align__(256) __nv_bfloat16 g_featL[N0 * F0];
__device__ __align__(256) float g_A [(size_t)N0 * N0];   // Gram matrix (lower tri valid)
__device__ __align__(256) float g_x [N0 * H];
__device__ __align__(256) float g_x2[N0 * H];
__device__ __align__(256) float g_y [N0 * H];
__device__ unsigned g_bits[N0 * (N0 / 32)];              // adjacency bitmask (2 MB)
__device__ float g_sq[N0];
__device__ float g_dis[N0];
__device__ float g_u[N0];
__device__ float g_v[N0];
__device__ float g_score[N0];
__device__ float g_vbi[N0];
__device__ int   g_perm[N0];
__device__ float g_vals[N0];
__device__ int   g_maxint;
__device__ float g_part[32 * 512];
// CSR adjacency (double-buffered across layers)
__device__ int g_colA[MAXE];
__device__ int g_colB[MAXE];
__device__ int g_rpA[N0 + 1];
__device__ int g_rpB[N0 + 1];
__device__ int g_deg[N0];
__device__ int g_inv[N0];

// ---------------- init ----------------
__global__ void k_init(float* out) {
    int t = blockIdx.x * blockDim.x + threadIdx.x;
    if (t < 512) out[t] = 0.0f;
    if (t == 0) g_maxint = 0;
}

// ---------------- pos MLP + concat + bf16 split + sqnorm (fused) ----------------
__global__ void k_posconcat(const float* __restrict__ feature,
                            const float* __restrict__ img,
                            const float* __restrict__ Wp,
                            const float* __restrict__ bp) {
    int n = blockIdx.x;
    int t = threadIdx.x;  // 128 threads
    const float* fr = feature + (size_t)n * 500;
    float* dst = g_feat + (size_t)n * F0;
    __nv_bfloat16* dH = g_featH + (size_t)n * F0;
    __nv_bfloat16* dL = g_featL + (size_t)n * F0;
    float ssq = 0.0f;
    for (int i = t; i < 500; i += 128) {
        float v = fr[i];
        dst[i] = v;
        __nv_bfloat16 h = __float2bfloat16(v);
        dH[i] = h;
        dL[i] = __float2bfloat16(v - __bfloat162float(h));
        ssq = fmaf(v, v, ssq);
    }
    if (t < 12) {
        float s = bp[t];
#pragma unroll
        for (int h = 0; h < 6; h++) s += img[n * 6 + h] * Wp[h * 12 + t];
        float v = fmaxf(s, 0.0f);
        dst[500 + t] = v;
        __nv_bfloat16 hh = __float2bfloat16(v);
        dH[500 + t] = hh;
        dL[500 + t] = __float2bfloat16(v - __bfloat162float(hh));
        ssq = fmaf(v, v, ssq);
    }
    __shared__ float sm[128];
    sm[t] = ssq; __syncthreads();
    for (int s = 64; s > 0; s >>= 1) {
        if (t < s) sm[t] += sm[t + s];
        __syncthreads();
    }
    if (t == 0) g_sq[n] = sm[0];
}

// ================= Gram via mma.sync bf16 (2-limb split, 3 products) =================
// cp.async 2-stage pipeline; C[128x128] per block; 8 warps 4(M)x2(N); warp tile 32x64.
// SMEM rows: 64 bf16 = 128B; granule (16B) swizzled: phys = g ^ (row&7).
__device__ __forceinline__ void cpasync16(uint32_t saddr, const void* gptr) {
    asm volatile("cp.async.cg.shared.global [%0], [%1], 16;\n" :: "r"(saddr), "l"(gptr));
}
__device__ __forceinline__ void ldmA4(uint32_t f[4], uint32_t base, int R, int g, int lane) {
    int lgrp = lane >> 3, lrow = lane & 7;
    int r = R + lrow + ((lgrp & 1) << 3);
    int gg = g + (lgrp >> 1);
    uint32_t addr = base + (r << 7) + ((gg ^ (r & 7)) << 4);
    asm volatile("ldmatrix.sync.aligned.m8n8.x4.shared.b16 {%0,%1,%2,%3}, [%4];"
        : "=r"(f[0]), "=r"(f[1]), "=r"(f[2]), "=r"(f[3]) : "r"(addr));
}
__device__ __forceinline__ void ldmB4(uint32_t f0[2], uint32_t f1[2],
                                      uint32_t base, int Nb, int g, int lane) {
    int lgrp = lane >> 3, lrow = lane & 7;
    int r = Nb + lrow + ((lgrp >> 1) << 3);
    int gg = g + (lgrp & 1);
    uint32_t addr = base + (r << 7) + ((gg ^ (r & 7)) << 4);
    uint32_t r0, r1, r2, r3;
    asm volatile("ldmatrix.sync.aligned.m8n8.x4.shared.b16 {%0,%1,%2,%3}, [%4];"
        : "=r"(r0), "=r"(r1), "=r"(r2), "=r"(r3) : "r"(addr));
    f0[0] = r0; f0[1] = r1; f1[0] = r2; f1[1] = r3;
}
__device__ __forceinline__ void mma16816(float c[4], const uint32_t a[4], const uint32_t b[2]) {
    asm volatile(
        "mma.sync.aligned.m16n8k16.row.col.f32.bf16.bf16.f32 "
        "{%0,%1,%2,%3}, {%4,%5,%6,%7}, {%8,%9}, {%0,%1,%2,%3};"
        : "+f"(c[0]), "+f"(c[1]), "+f"(c[2]), "+f"(c[3])
        : "r"(a[0]), "r"(a[1]), "r"(a[2]), "r"(a[3]), "r"(b[0]), "r"(b[1]));
}

__global__ __launch_bounds__(256) void k_gram_mma(float* __restrict__ C) {
    int bx = blockIdx.x, by = blockIdx.y;
    if (bx > by) return;                 // lower triangle blocks only
    int m0 = by * 128, n0 = bx * 128;

    extern __shared__ __align__(16) __nv_bfloat16 smem[];  // 2 stages x (A 16KB + B 16KB)
    uint32_t sbase = (uint32_t)__cvta_generic_to_shared(smem);

    int tid = threadIdx.x;
    int wid = tid >> 5, lane = tid & 31;
    int wm0 = (wid & 3) * 32;            // warp M offset
    int wn0 = (wid >> 2) * 64;           // warp N offset

    float c[2][8][4];
#pragma unroll
    for (int mf = 0; mf < 2; mf++)
#pragma unroll
        for (int nf = 0; nf < 8; nf++)
#pragma unroll
            for (int q = 0; q < 4; q++) c[mf][nf][q] = 0.0f;

    auto stage = [&](int k0, int s) {
        uint32_t bA = sbase + (uint32_t)s * 32768u;
        uint32_t bB = bA + 16384u;
#pragma unroll
        for (int i = tid; i < 1024; i += 256) {
            int r = i >> 3, g = i & 7;
            const __nv_bfloat16 *pa, *pb;
            if (g < 4) {
                pa = g_featH + (size_t)(m0 + r) * F0 + k0 + g * 8;
                pb = g_featH + (size_t)(n0 + r) * F0 + k0 + g * 8;
            } else {
                pa = g_featL + (size_t)(m0 + r) * F0 + k0 + (g - 4) * 8;
                pb = g_featL + (size_t)(n0 + r) * F0 + k0 + (g - 4) * 8;
            }
            uint32_t off = (uint32_t)((r * 64 + ((g ^ (r & 7)) << 3)) * 2);
            cpasync16(bA + off, pa);
            cpasync16(bB + off, pb);
        }
        asm volatile("cp.async.commit_group;\n" ::: "memory");
    };

    stage(0, 0);
    for (int it = 0; it < 16; it++) {
        int s = it & 1;
        if (it + 1 < 16) {
            stage((it + 1) * 32, s ^ 1);
            asm volatile("cp.async.wait_group 1;\n" ::: "memory");
        } else {
            asm volatile("cp.async.wait_group 0;\n" ::: "memory");
        }
        __syncthreads();
        uint32_t sAu = sbase + (uint32_t)s * 32768u;
        uint32_t sBu = sAu + 16384u;
#pragma unroll
        for (int st = 0; st < 2; st++) {    // two k16 steps per 32-chunk
            int gh = st * 2, gl = 4 + st * 2;
            uint32_t ah[2][4], al[2][4];
            ldmA4(ah[0], sAu, wm0,      gh, lane);
            ldmA4(ah[1], sAu, wm0 + 16, gh, lane);
            ldmA4(al[0], sAu, wm0,      gl, lane);
            ldmA4(al[1], sAu, wm0 + 16, gl, lane);
            uint32_t bh[8][2], bl[8][2];
#pragma unroll
            for (int n2 = 0; n2 < 4; n2++) {
                ldmB4(bh[2 * n2], bh[2 * n2 + 1], sBu, wn0 + n2 * 16, gh, lane);
                ldmB4(bl[2 * n2], bl[2 * n2 + 1], sBu, wn0 + n2 * 16, gl, lane);
            }
#pragma unroll
            for (int mf = 0; mf < 2; mf++)
#pragma unroll
                for (int nf = 0; nf < 8; nf++) {
                    mma16816(c[mf][nf], ah[mf], bh[nf]);  // hi*hi
                    mma16816(c[mf][nf], ah[mf], bl[nf]);  // hi*lo
                    mma16816(c[mf][nf], al[mf], bh[nf]);  // lo*hi
                }
        }
        __syncthreads();
    }

    // epilogue: store + fused d2 max (strictly lower elements only)
    __shared__ float wmax[8];
    float dmax = 0.0f;
    int rbase = m0 + wm0 + (lane >> 2);
    int cbase = n0 + wn0 + ((lane & 3) << 1);
#pragma unroll
    for (int mf = 0; mf < 2; mf++) {
        int r = rbase + mf * 16;
        float sr0 = g_sq[r], sr8 = g_sq[r + 8];
#pragma unroll
        for (int nf = 0; nf < 8; nf++) {
            int cc = cbase + nf * 8;
            float v0 = c[mf][nf][0], v1 = c[mf][nf][1];
            float v2 = c[mf][nf][2], v3 = c[mf][nf][3];
            *(float2*)&C[(size_t)r * N0 + cc]       = make_float2(v0, v1);
            *(float2*)&C[(size_t)(r + 8) * N0 + cc] = make_float2(v2, v3);
            float sc0 = g_sq[cc], sc1 = g_sq[cc + 1];
            if (cc     < r)     dmax = fmaxf(dmax, sr0 + sc0 - 2.0f * v0);
            if (cc + 1 < r)     dmax = fmaxf(dmax, sr0 + sc1 - 2.0f * v1);
            if (cc     < r + 8) dmax = fmaxf(dmax, sr8 + sc0 - 2.0f * v2);
            if (cc + 1 < r + 8) dmax = fmaxf(dmax, sr8 + sc1 - 2.0f * v3);
        }
    }
#pragma unroll
    for (int off = 16; off; off >>= 1)
        dmax = fmaxf(dmax, __shfl_xor_sync(0xFFFFFFFFu, dmax, off));
    if (lane == 0) wmax[wid] = dmax;
    __syncthreads();
    if (tid == 0) {
        float m = wmax[0];
#pragma unroll
        for (int w = 1; w < 8; w++) m = fmaxf(m, wmax[w]);
        atomicMax(&g_maxint, __float_as_int(fmaxf(m, 0.0f)));
    }
}

// ---------------- skinny SGEMM 64x64 tile: C = dis[m] * (A[M,K] @ B[K,N]) ----------------
__global__ __launch_bounds__(256) void k_sgemm64(
    const float* __restrict__ A, const float* __restrict__ B, float* __restrict__ C,
    int M, int N, int K, const float* __restrict__ dis)
{
    __shared__ float As[16][68];
    __shared__ float Bs[16][68];
    int tid = threadIdx.x;
    int m0 = blockIdx.y * 64, n0 = blockIdx.x * 64;
    int tx = tid & 15, ty = tid >> 4;
    float acc[4][4];
#pragma unroll
    for (int i = 0; i < 4; i++)
#pragma unroll
        for (int j = 0; j < 4; j++) acc[i][j] = 0.0f;

    int arow = tid >> 2, akc = (tid & 3) * 4;
    int brow = tid >> 4, bc = (tid & 15) * 4;

    for (int k0 = 0; k0 < K; k0 += 16) {
        float4 av = *(const float4*)(A + (size_t)(m0 + arow) * K + k0 + akc);
        As[akc + 0][arow] = av.x; As[akc + 1][arow] = av.y;
        As[akc + 2][arow] = av.z; As[akc + 3][arow] = av.w;
        float4 bv = *(const float4*)(B + (size_t)(k0 + brow) * N + n0 + bc);
        *(float4*)&Bs[brow][bc] = bv;
        __syncthreads();
#pragma unroll
        for (int kk = 0; kk < 16; kk++) {
            float a[4], b[4];
#pragma unroll
            for (int i = 0; i < 4; i++) a[i] = As[kk][ty * 4 + i];
#pragma unroll
            for (int j = 0; j < 4; j++) b[j] = Bs[kk][tx * 4 + j];
#pragma unroll
            for (int i = 0; i < 4; i++)
#pragma unroll
                for (int j = 0; j < 4; j++)
                    acc[i][j] = fmaf(a[i], b[j], acc[i][j]);
        }
        __syncthreads();
    }
#pragma unroll
    for (int i = 0; i < 4; i++) {
        int m = m0 + ty * 4 + i;
        float d = dis[m];
#pragma unroll
        for (int j = 0; j < 4; j++)
            C[(size_t)m * N + n0 + tx * 4 + j] = d * acc[i][j];
    }
}

// ---------------- degree + adjacency bitmask (single Gram pass) ----------------
__global__ void k_degree() {
    int j = blockIdx.x, t = threadIdx.x;  // 256 threads, 8 warps
    int warp = t >> 5, lane = t & 31;
    float thr = 0.5f * __int_as_float(g_maxint);
    float sj = g_sq[j];
    const float* row = g_A + (size_t)j * N0;
    int cnt = 0;
    for (int wd = warp; wd < N0 / 32; wd += 8) {
        int i = wd * 32 + lane;
        bool pred = (i < j) && (sj + g_sq[i] - 2.0f * row[i] < thr);
        unsigned m = __ballot_sync(0xFFFFFFFFu, pred);
        if (lane == 0) g_bits[j * (N0 / 32) + wd] = m;
        cnt += pred ? 1 : 0;
    }
    __shared__ int sm[256];
    sm[t] = cnt; __syncthreads();
    for (int s = 128; s > 0; s >>= 1) {
        if (t < s) sm[t] += sm[t + s];
        __syncthreads();
    }
    if (t == 0) { g_deg[j] = sm[0]; g_dis[j] = rsqrtf(1.0f + (float)sm[0]); }
}

// ---------------- exclusive scan of degrees -> row pointers (single block) ----------------
__global__ __launch_bounds__(1024) void k_scan(const int* __restrict__ deg,
                                               int* __restrict__ rp, int n) {
    __shared__ int s[1024];
    int t = threadIdx.x;
    int base = t * 4;
    int v[4]; int local = 0;
#pragma unroll
    for (int q = 0; q < 4; q++) {
        int idx = base + q;
        v[q] = (idx < n) ? deg[idx] : 0;
        local += v[q];
    }
    s[t] = local; __syncthreads();
    for (int off = 1; off < 1024; off <<= 1) {
        int val = (t >= off) ? s[t - off] : 0;
        __syncthreads();
        s[t] += val;
        __syncthreads();
    }
    int run = (t == 0) ? 0 : s[t - 1];
#pragma unroll
    for (int q = 0; q < 4; q++) {
        int idx = base + q;
        if (idx < n) rp[idx] = run;
        run += v[q];
    }
    if (t == 1023) rp[n] = s[1023];
}

// ---------------- fill initial CSR from bitmask: warp per row ----------------
__global__ void k_fillcsr(const int* __restrict__ rp, int* __restrict__ col, int Nl) {
    int w = (blockIdx.x * blockDim.x + threadIdx.x) >> 5;
    int lane = threadIdx.x & 31;
    if (w >= Nl) return;
    int base = rp[w];
    int nw = (w + 31) >> 5;   // words covering cols < w
    for (int wd = 0; wd < nw; wd++) {
        unsigned m = g_bits[w * (N0 / 32) + wd];
        bool pred = (m >> lane) & 1u;
        if (pred) col[base + __popc(m & ((1u << lane) - 1u))] = wd * 32 + lane;
        base += __popc(m);
    }
}

// -------- SpMM + GCN epilogue + fused scorer: xnew, u = xnew@Wn, v = xnew@Wr --------
__global__ void k_spmm(const int* __restrict__ rp, const int* __restrict__ col,
                       const float* __restrict__ y, float* __restrict__ xnew,
                       const float* __restrict__ bias,
                       const float* __restrict__ Wn, const float* __restrict__ Wr) {
    int j = blockIdx.x, t = threadIdx.x;  // 256 threads = H
    int p = rp[j], e = rp[j + 1];
    float acc = y[(size_t)j * H + t];     // self loop
    for (; p + 4 <= e; p += 4) {
        int c0 = col[p], c1 = col[p + 1], c2 = col[p + 2], c3 = col[p + 3];
        acc += y[(size_t)c0 * H + t] + y[(size_t)c1 * H + t]
             + y[(size_t)c2 * H + t] + y[(size_t)c3 * H + t];
    }
    for (; p < e; ++p) acc += y[(size_t)col[p] * H + t];
    float xv = fmaxf(g_dis[j] * acc + bias[t], 0.0f);
    xnew[(size_t)j * H + t] = xv;
    // fused scorer matvecs
    __shared__ float su[256], sv[256];
    su[t] = xv * Wn[t]; sv[t] = xv * Wr[t]; __syncthreads();
    for (int s = 128; s > 0; s >>= 1) {
        if (t < s) { su[t] += su[t + s]; sv[t] += sv[t + s]; }
        __syncthreads();
    }
    if (t == 0) { g_u[j] = su[0]; g_v[j] = sv[0]; }
}

// ---------------- score = tanh(A@u + bs + v): warp per row over CSR ----------------
__global__ void k_auscore(const int* __restrict__ rp, const int* __restrict__ col,
                          const float* __restrict__ bsp, int Nl) {
    int w = (blockIdx.x * blockDim.x + threadIdx.x) >> 5;
    int lane = threadIdx.x & 31;
    if (w >= Nl) return;
    int s = rp[w], e = rp[w + 1];
    float acc = 0.0f;
    for (int p = s + lane; p < e; p += 32) acc += g_u[col[p]];
    for (int off = 16; off; off >>= 1) acc += __shfl_down_sync(0xFFFFFFFFu, acc, off);
    if (lane == 0) g_score[w] = tanhf(acc + bsp[0] + g_v[w]);
}

// ---------------- top-k: bitonic sort by score, then flag+scan compaction ----------------
__device__ void bitonic4096(float* ss, int* si) {
    int t = threadIdx.x;
    for (int size = 2; size <= 4096; size <<= 1) {
        for (int stride = size >> 1; stride > 0; stride >>= 1) {
            __syncthreads();
            for (int p = t; p < 2048; p += 1024) {
                int i = ((p / stride) * (stride << 1)) + (p % stride);
                int j = i + stride;
                bool dirUp = ((i & size) == 0);
                float sa = ss[i], sb = ss[j];
                int ia = si[i], ib = si[j];
                bool b = (sb > sa) || (sb == sa && ib < ia);  // desc by score, tie -> lower idx
                if (b == dirUp) {
                    ss[i] = sb; ss[j] = sa;
                    si[i] = ib; si[j] = ia;
                }
            }
        }
    }
    __syncthreads();
}

__global__ __launch_bounds__(1024) void k_topk(int Nl, int k) {
    __shared__ float ss[4096];
    __shared__ int   si[4096];
    __shared__ unsigned char fl[4096];
    __shared__ int   sc[1024];
    int t = threadIdx.x;
    for (int i = t; i < 4096; i += 1024) {
        if (i < Nl) { ss[i] = g_score[i]; si[i] = i; }
        else        { ss[i] = __int_as_float(0xff800000); si[i] = 0x7FFFFFFF; }
        fl[i] = 0;
    }
    __syncthreads();
    bitonic4096(ss, si);                       // descending by score
    for (int r = t; r < k; r += 1024) {        // mark selected originals
        int idx = si[r];
        fl[idx] = 1;
        g_vbi[idx] = ss[r];
    }
    __syncthreads();
    // stable compaction by ascending original index via prefix scan
    int base = t * 4;
    int v[4]; int local = 0;
#pragma unroll
    for (int q = 0; q < 4; q++) { v[q] = fl[base + q]; local += v[q]; }
    sc[t] = local; __syncthreads();
    for (int off = 1; off < 1024; off <<= 1) {
        int val = (t >= off) ? sc[t - off] : 0;
        __syncthreads();
        sc[t] += val;
        __syncthreads();
    }
    int run = (t == 0) ? 0 : sc[t - 1];
#pragma unroll
    for (int q = 0; q < 4; q++) {
        if (v[q]) { g_perm[run] = base + q; g_vals[run] = g_vbi[base + q]; }
        run += v[q];
    }
}

// ---------------- gather x: xp[r] = x[perm[r]] * vals[r] ----------------
__global__ void k_gatherx(const float* __restrict__ xin, float* __restrict__ xout, int k) {
    int r = blockIdx.x, t = threadIdx.x;
    int pr = g_perm[r];
    float v = g_vals[r];
    xout[(size_t)r * H + t] = xin[(size_t)pr * H + t] * v;
}

// ---------------- inverse permutation ----------------
__global__ void k_invreset(int Nl) {
    int i = blockIdx.x * blockDim.x + threadIdx.x;
    if (i < Nl) g_inv[i] = -1;
}
__global__ void k_invset(int k) {
    int r = blockIdx.x * blockDim.x + threadIdx.x;
    if (r < k) g_inv[g_perm[r]] = r;
}

// ---------------- pooled CSR: count surviving neighbors per pooled row ----------------
__global__ void k_deg2(const int* __restrict__ rpIn, const int* __restrict__ colIn, int k) {
    int w = (blockIdx.x * blockDim.x + threadIdx.x) >> 5;
    int lane = threadIdx.x & 31;
    if (w >= k) return;
    int pr = g_perm[w];
    int s = rpIn[pr], e = rpIn[pr + 1];
    int cnt = 0;
    for (int p = s + lane; p < e; p += 32) cnt += (g_inv[colIn[p]] >= 0) ? 1 : 0;
    for (int off = 16; off; off >>= 1) cnt += __shfl_down_sync(0xFFFFFFFFu, cnt, off);
    if (lane == 0) { g_deg[w] = cnt; g_dis[w] = rsqrtf(1.0f + (float)cnt); }
}

// ---------------- pooled CSR: fill (ordered; ascending old -> ascending new) ----------------
__global__ void k_fill2(const int* __restrict__ rpIn, const int* __restrict__ colIn,
                        const int* __restrict__ rpOut, int* __restrict__ colOut, int k) {
    int w = (blockIdx.x * blockDim.x + threadIdx.x) >> 5;
    int lane = threadIdx.x & 31;
    if (w >= k) return;
    int pr = g_perm[w];
    int s = rpIn[pr], e = rpIn[pr + 1];
    int base = rpOut[w];
    for (int p0 = s; p0 < e; p0 += 32) {
        int p = p0 + lane;
        int m = -1;
        bool pred = false;
        if (p < e) { m = g_inv[colIn[p]]; pred = (m >= 0); }
        unsigned mask = __ballot_sync(0xFFFFFFFFu, pred);
        if (pred) colOut[base + __popc(mask & ((1u << lane) - 1u))] = m;
        base += __popc(mask);
    }
}

// ---------------- readout: column max + sum -> accumulate into out ----------------
__global__ void k_readout_part(const float* __restrict__ x, int k) {
    int b = blockIdx.x, t = threadIdx.x;  // grid 32, 256 threads
    float mx = __int_as_float(0xff800000), sm = 0.0f;
    for (int r = b; r < k; r += 32) {
        float v = x[(size_t)r * H + t];
        mx = fmaxf(mx, v);
        sm += v;
    }
    g_part[b * 512 + t] = mx;
    g_part[b * 512 + 256 + t] = sm;
}

__global__ void k_readout_final(float* out, float invk) {
    int t = threadIdx.x;  // 256
    float mx = __int_as_float(0xff800000), sm = 0.0f;
    for (int b = 0; b < 32; b++) {
        mx = fmaxf(mx, g_part[b * 512 + t]);
        sm += g_part[b * 512 + 256 + t];
    }
    out[t] += mx;
    out[256 + t] += sm * invk;
}

// ---------------- one GCN + SAGPool + readout layer (CSR adjacency) ----------------
static void run_layer(const float* xin, int Kin, const int* rpIn, const int* colIn, int Nl,
                      const float* W, const float* bvec,
                      const float* Wr, const float* Wn, const float* bs,
                      int k, float* xnew, float* xpool,
                      int* rpOut, int* colOut, int* pdeg,
                      float* ybuf, const float* pdis, float* d_out)
{
    // y = dis .* (x @ W)
    {
        dim3 g(H / 64, Nl / 64);
        k_sgemm64<<<g, 256>>>(xin, W, ybuf, Nl, H, Kin, pdis);
    }
    // xnew = relu(dis .* (A@y + y) + b) + fused scorer matvecs
    k_spmm<<<Nl, 256>>>(rpIn, colIn, ybuf, xnew, bvec, Wn, Wr);
    k_auscore<<<(Nl + 7) / 8, 256>>>(rpIn, colIn, bs, Nl);
    k_topk<<<1, 1024>>>(Nl, k);
    k_gatherx<<<k, 256>>>(xnew, xpool, k);
    // pooled CSR
    k_invreset<<<(Nl + 255) / 256, 256>>>(Nl);
    k_invset<<<(k + 255) / 256, 256>>>(k);
    k_deg2<<<(k + 7) / 8, 256>>>(rpIn, colIn, k);
    k_scan<<<1, 1024>>>(pdeg, rpOut, k);
    k_fill2<<<(k + 7) / 8, 256>>>(rpIn, colIn, rpOut, colOut, k);
    // readout accumulate
    k_readout_part<<<32, 256>>>(xpool, k);
    k_readout_final<<<1, 256>>>(d_out, 1.0f / (float)k);
}

extern "C" void kernel_launch(void* const* d_in, const int* in_sizes, int n_in,
                              void* d_out, int out_size) {
    const float* feature = (const float*)d_in[0];
    const float* img     = (const float*)d_in[1];
    const float* W_pos   = (const float*)d_in[2];
    const float* b_pos   = (const float*)d_in[3];
    const float* W1 = (const float*)d_in[4];  const float* b1 = (const float*)d_in[5];
    const float* W2 = (const float*)d_in[6];  const float* b2 = (const float*)d_in[7];
    const float* W3 = (const float*)d_in[8];  const float* b3 = (const float*)d_in[9];
    const float* Wr1 = (const float*)d_in[10]; const float* Wn1 = (const float*)d_in[11];
    const float* bs1 = (const float*)d_in[12];
    const float* Wr2 = (const float*)d_in[13]; const float* Wn2 = (const float*)d_in[14];
    const float* bs2 = (const float*)d_in[15];
    const float* Wr3 = (const float*)d_in[16]; const float* Wn3 = (const float*)d_in[17];
    const float* bs3 = (const float*)d_in[18];
    float* out = (float*)d_out;

    float *pfeat, *pA, *px, *px2, *py, *pdis;
    int *pcolA, *pcolB, *prpA, *prpB, *pdeg;
    cudaGetSymbolAddress((void**)&pfeat, g_feat);
    cudaGetSymbolAddress((void**)&pA,    g_A);
    cudaGetSymbolAddress((void**)&px,    g_x);
    cudaGetSymbolAddress((void**)&px2,   g_x2);
    cudaGetSymbolAddress((void**)&py,    g_y);
    cudaGetSymbolAddress((void**)&pdis,  g_dis);
    cudaGetSymbolAddress((void**)&pcolA, g_colA);
    cudaGetSymbolAddress((void**)&pcolB, g_colB);
    cudaGetSymbolAddress((void**)&prpA,  g_rpA);
    cudaGetSymbolAddress((void**)&prpB,  g_rpB);
    cudaGetSymbolAddress((void**)&pdeg,  g_deg);

    cudaFuncSetAttribute(k_gram_mma, cudaFuncAttributeMaxDynamicSharedMemorySize, 65536);

    k_init<<<2, 256>>>(out);
    k_posconcat<<<N0, 128>>>(feature, img, W_pos, b_pos);   // + bf16 split + sqnorm

    // Gram lower triangle via bf16 2-limb tensor-core MMA (cp.async pipelined),
    // fused d2-max epilogue sets g_maxint
    {
        dim3 g(N0 / 128, N0 / 128);
        k_gram_mma<<<g, 256, 65536>>>(pA);
    }
    // adjacency: degree + bitmask in one Gram pass, then CSR fill from bitmask
    k_degree<<<N0, 256>>>();
    k_scan<<<1, 1024>>>(pdeg, prpA, N0);
    k_fillcsr<<<N0 / 8, 256>>>(prpA, pcolA, N0);

    // layer 1: CSR A (4096) -> pooled CSR B (3072)
    run_layer(pfeat, F0, prpA, pcolA, N0,  W1, b1, Wr1, Wn1, bs1, KP1,
              px, px2, prpB, pcolB, pdeg, py, pdis, out);
    // layer 2: CSR B (3072) -> pooled CSR A (2304)
    run_layer(px2, H, prpB, pcolB, KP1, W2, b2, Wr2, Wn2, bs2, KP2,
              px, px2, prpA, pcolA, pdeg, py, pdis, out);
    // layer 3: CSR A (2304) -> pooled CSR B (1728)
    run_layer(px2, H, prpA, pcolA, KP2, W3, b3, Wr3, Wn3, bs3, KP3,
              px, px2, prpB, pcolB, pdeg, py, pdis, out);
}